// round 4
// baseline (speedup 1.0000x reference)
#include <cuda_runtime.h>

#define FIN   128
#define FHID  64
#define NROW  1024
#define MROWS (NROW*NROW)
#define EPSV  1e-5f
#define ALPHA 0.2f
#define NEGV  -9e15f

// ---------------- scratch (device globals: no allocation allowed) ----------
__device__ float g_sum1[FIN],  g_sumsq1[FIN];
__device__ float g_Wp[FIN*FHID], g_bp[FHID];
__device__ float g_sum2[FHID], g_sumsq2[FHID];
__device__ float g_sc2[FHID],  g_bi2[FHID];
__device__ float g_s3[2];
__device__ float g_eaff[2];
__device__ float g_y[(size_t)MROWS*FHID];   // 256 MB scratch for pre-BN2 activations
__device__ float g_s[MROWS];                // 4 MB pre-BN3 scalars

// ---------------- packed f32x2 helpers (FFMA2 path, sm_100+) ---------------
__device__ __forceinline__ unsigned long long pack2(float lo, float hi) {
    unsigned long long r;
    asm("mov.b64 %0, {%1, %2};" : "=l"(r) : "f"(lo), "f"(hi));
    return r;
}
__device__ __forceinline__ float2 unpack2(unsigned long long v) {
    float2 f;
    asm("mov.b64 {%0, %1}, %2;" : "=f"(f.x), "=f"(f.y) : "l"(v));
    return f;
}
__device__ __forceinline__ unsigned long long ffma2(unsigned long long a,
                                                    unsigned long long b,
                                                    unsigned long long c) {
    unsigned long long d;
    asm("fma.rn.f32x2 %0, %1, %2, %3;" : "=l"(d) : "l"(a), "l"(b), "l"(c));
    return d;
}
__device__ __forceinline__ unsigned long long add2(unsigned long long a,
                                                   unsigned long long b) {
    unsigned long long d;
    asm("add.rn.f32x2 %0, %1, %2;" : "=l"(d) : "l"(a), "l"(b));
    return d;
}
__device__ __forceinline__ unsigned long long mul2(unsigned long long a,
                                                   unsigned long long b) {
    unsigned long long d;
    asm("mul.rn.f32x2 %0, %1, %2;" : "=l"(d) : "l"(a), "l"(b));
    return d;
}

__device__ __forceinline__ float leakyf(float v) { return v >= 0.f ? v : ALPHA * v; }

// ---------------- K0: zero accumulators ------------------------------------
__global__ void k_zero() {
    int t = threadIdx.x;  // 128 threads
    if (t < FIN)  { g_sum1[t] = 0.f; g_sumsq1[t] = 0.f; }
    if (t < FHID) { g_sum2[t] = 0.f; g_sumsq2[t] = 0.f; }
    if (t < 2)    { g_s3[t] = 0.f; }
}

// ---------------- K1: per-feature sum / sumsq over 1M rows ------------------
__global__ void k_colstats(const float4* __restrict__ x) {
    __shared__ float shS[8 * FIN], shQ[8 * FIN];
    int tid = threadIdx.x, lane = tid & 31, w = tid >> 5;  // 256 thr = 8 warps
    float4 s = make_float4(0.f, 0.f, 0.f, 0.f);
    float4 q = make_float4(0.f, 0.f, 0.f, 0.f);
    for (int r = blockIdx.x * 8 + w; r < MROWS; r += gridDim.x * 8) {
        float4 v = x[(size_t)r * (FIN / 4) + lane];
        s.x += v.x; s.y += v.y; s.z += v.z; s.w += v.w;
        q.x += v.x * v.x; q.y += v.y * v.y; q.z += v.z * v.z; q.w += v.w * v.w;
    }
    ((float4*)(shS + w * FIN))[lane] = s;
    ((float4*)(shQ + w * FIN))[lane] = q;
    __syncthreads();
    if (tid < FIN) {
        float a = 0.f, b = 0.f;
        #pragma unroll
        for (int ww = 0; ww < 8; ww++) { a += shS[ww * FIN + tid]; b += shQ[ww * FIN + tid]; }
        atomicAdd(&g_sum1[tid], a);
        atomicAdd(&g_sumsq1[tid], b);
    }
}

// ---------------- K2: fold BN1 into W --------------------------------------
__global__ void k_fin1(const float* __restrict__ W, const float* __restrict__ g1,
                       const float* __restrict__ b1) {
    __shared__ float s1[FIN], t1[FIN];
    int tid = threadIdx.x;  // 128
    float inv = 1.f / (float)MROWS;
    float mu  = g_sum1[tid] * inv;
    float var = g_sumsq1[tid] * inv - mu * mu;
    float rs  = rsqrtf(var + EPSV);
    float sc  = g1[tid] * rs;
    s1[tid] = sc;
    t1[tid] = b1[tid] - mu * sc;
    __syncthreads();
    float sv = s1[tid];
    for (int h = 0; h < FHID; h++) g_Wp[tid * FHID + h] = sv * W[tid * FHID + h];
    if (tid < FHID) {
        float acc = 0.f;
        for (int f = 0; f < FIN; f++) acc += t1[f] * W[f * FHID + tid];
        g_bp[tid] = acc;
    }
}

// ---------------- K3: GEMM y = x@Wp + bp  (+ y stats), FFMA2 ----------------
__global__ __launch_bounds__(256, 2) void k_gemm(const float* __restrict__ x) {
    __shared__ float sW[FIN * FHID];               // 32 KB
    __shared__ unsigned long long sB[FHID / 2];
    __shared__ float sS[FHID], sQ[FHID];
    int tid = threadIdx.x, lane = tid & 31;
    for (int i = tid; i < FIN * FHID / 4; i += 256)
        ((float4*)sW)[i] = ((const float4*)g_Wp)[i];
    if (tid < FHID / 2) sB[tid] = pack2(g_bp[2 * tid], g_bp[2 * tid + 1]);
    if (tid < FHID) { sS[tid] = 0.f; sQ[tid] = 0.f; }
    __syncthreads();

    size_t row = (size_t)blockIdx.x * 256 + tid;        // exactly 1M threads
    const float4* xr = (const float4*)(x + row * FIN);

    unsigned long long acc[FHID / 2];                   // 32 packed f32x2 = all 64 h
    #pragma unroll
    for (int j = 0; j < FHID / 2; j++) acc[j] = sB[j];

    #pragma unroll 2
    for (int kc = 0; kc < FIN / 4; kc++) {
        float4 xv = xr[kc];
        #pragma unroll
        for (int s = 0; s < 4; s++) {
            float xk = (s == 0) ? xv.x : (s == 1) ? xv.y : (s == 2) ? xv.z : xv.w;
            unsigned long long x2 = pack2(xk, xk);
            const ulonglong2* wk = (const ulonglong2*)(sW + (kc * 4 + s) * FHID);
            #pragma unroll
            for (int q = 0; q < 16; q++) {             // 16 x ulonglong2 = 64 floats
                ulonglong2 wv = wk[q];                 // broadcast LDS.128
                acc[2 * q]     = ffma2(x2, wv.x, acc[2 * q]);
                acc[2 * q + 1] = ffma2(x2, wv.y, acc[2 * q + 1]);
            }
        }
    }

    // store y directly from packed accs (no y[] array -> no spills)
    float4* yr = (float4*)(g_y + row * FHID);
    #pragma unroll
    for (int j = 0; j < FHID / 4; j++) {
        float2 f0 = unpack2(acc[2 * j]);
        float2 f1 = unpack2(acc[2 * j + 1]);
        yr[j] = make_float4(f0.x, f0.y, f1.x, f1.y);
    }

    // packed per-feature warp reduction: lane j ends owning features (2j, 2j+1)
    #pragma unroll
    for (int j = 0; j < FHID / 2; j++) {
        unsigned long long v = acc[j];
        unsigned long long q = mul2(v, v);
        #pragma unroll
        for (int o = 16; o; o >>= 1) {
            v = add2(v, __shfl_xor_sync(0xffffffffu, v, o));
            q = add2(q, __shfl_xor_sync(0xffffffffu, q, o));
        }
        if (lane == j) {
            float2 s2 = unpack2(v), q2 = unpack2(q);
            atomicAdd(&sS[2 * j],     s2.x);
            atomicAdd(&sS[2 * j + 1], s2.y);
            atomicAdd(&sQ[2 * j],     q2.x);
            atomicAdd(&sQ[2 * j + 1], q2.y);
        }
    }
    __syncthreads();
    if (tid < FHID) {
        atomicAdd(&g_sum2[tid], sS[tid]);
        atomicAdd(&g_sumsq2[tid], sQ[tid]);
    }
}

// ---------------- K4: finalize BN2 affine ----------------------------------
__global__ void k_fin2(const float* __restrict__ g2, const float* __restrict__ b2) {
    int tid = threadIdx.x;  // 64
    float inv = 1.f / (float)MROWS;
    float mu  = g_sum2[tid] * inv;
    float var = g_sumsq2[tid] * inv - mu * mu;
    float rs  = rsqrtf(var + EPSV);
    float sc  = g2[tid] * rs;
    g_sc2[tid] = sc;
    g_bi2[tid] = b2[tid] - mu * sc;
}

// ---------------- K5: s = leaky(bn2(y)) @ a  (+ s stats) --------------------
__global__ void k_rowdot(const float* __restrict__ a_vec) {
    __shared__ float sc[FHID], sb[FHID], sa[FHID];
    __shared__ float redS[8], redQ[8];
    int tid = threadIdx.x, lane = tid & 31, w = tid >> 5;  // 256 thr
    if (tid < FHID) { sc[tid] = g_sc2[tid]; sb[tid] = g_bi2[tid]; sa[tid] = a_vec[tid]; }
    __syncthreads();
    int h0 = 2 * lane, h1 = h0 + 1;
    float c0 = sc[h0], b0 = sb[h0], A0 = sa[h0];
    float c1 = sc[h1], b1 = sb[h1], A1 = sa[h1];
    float ps = 0.f, pq = 0.f;
    for (int r = blockIdx.x * 8 + w; r < MROWS; r += gridDim.x * 8) {
        float2 v = ((const float2*)(g_y + (size_t)r * FHID))[lane];
        float z0 = leakyf(v.x * c0 + b0);
        float z1 = leakyf(v.y * c1 + b1);
        float t  = A0 * z0 + A1 * z1;
        #pragma unroll
        for (int o = 16; o; o >>= 1) t += __shfl_xor_sync(0xffffffffu, t, o);
        if (lane == 0) { g_s[r] = t; ps += t; pq += t * t; }
    }
    if (lane == 0) { redS[w] = ps; redQ[w] = pq; }
    __syncthreads();
    if (tid == 0) {
        float S = 0.f, Q = 0.f;
        #pragma unroll
        for (int i = 0; i < 8; i++) { S += redS[i]; Q += redQ[i]; }
        atomicAdd(&g_s3[0], S);
        atomicAdd(&g_s3[1], Q);
    }
}

// ---------------- K6: finalize BN3 affine ----------------------------------
__global__ void k_fin3(const float* __restrict__ g3, const float* __restrict__ b3) {
    float inv = 1.f / (float)MROWS;
    float mu  = g_s3[0] * inv;
    float var = g_s3[1] * inv - mu * mu;
    float rs  = rsqrtf(var + EPSV);
    float c   = g3[0] * rs;
    g_eaff[0] = c;
    g_eaff[1] = b3[0] - mu * c;
}

// ---------------- K7: masked row softmax ------------------------------------
__global__ void k_softmax(const float* __restrict__ adj_mean, float* __restrict__ out) {
    __shared__ float redm[8], reds[8];
    int row = blockIdx.x, tid = threadIdx.x, lane = tid & 31, w = tid >> 5;  // 256 thr
    float c3 = g_eaff[0], d3 = g_eaff[1];
    const float4* sp = (const float4*)(g_s + (size_t)row * NROW);
    const float4* mp = (const float4*)(adj_mean + (size_t)row * NROW);
    float4 sv = sp[tid];
    float4 mv = mp[tid];
    float v0 = (mv.x > 0.f) ? leakyf(sv.x * c3 + d3) : NEGV;
    float v1 = (mv.y > 0.f) ? leakyf(sv.y * c3 + d3) : NEGV;
    float v2 = (mv.z > 0.f) ? leakyf(sv.z * c3 + d3) : NEGV;
    float v3 = (mv.w > 0.f) ? leakyf(sv.w * c3 + d3) : NEGV;

    float m = fmaxf(fmaxf(v0, v1), fmaxf(v2, v3));
    #pragma unroll
    for (int o = 16; o; o >>= 1) m = fmaxf(m, __shfl_xor_sync(0xffffffffu, m, o));
    if (lane == 0) redm[w] = m;
    __syncthreads();
    if (tid < 8) {
        float t = redm[tid];
        #pragma unroll
        for (int o = 4; o; o >>= 1) t = fmaxf(t, __shfl_xor_sync(0xffu, t, o));
        if (tid == 0) redm[0] = t;
    }
    __syncthreads();
    float rm = redm[0];

    float p0 = expf(v0 - rm), p1 = expf(v1 - rm), p2 = expf(v2 - rm), p3 = expf(v3 - rm);
    float s = p0 + p1 + p2 + p3;
    #pragma unroll
    for (int o = 16; o; o >>= 1) s += __shfl_xor_sync(0xffffffffu, s, o);
    if (lane == 0) reds[w] = s;
    __syncthreads();
    if (tid < 8) {
        float t = reds[tid];
        #pragma unroll
        for (int o = 4; o; o >>= 1) t += __shfl_xor_sync(0xffu, t, o);
        if (tid == 0) reds[0] = t;
    }
    __syncthreads();
    float invs = 1.f / reds[0];

    ((float4*)(out + (size_t)row * NROW))[tid] =
        make_float4(p0 * invs, p1 * invs, p2 * invs, p3 * invs);
}

// ---------------- launcher ---------------------------------------------------
extern "C" void kernel_launch(void* const* d_in, const int* in_sizes, int n_in,
                              void* d_out, int out_size) {
    const float* adj      = (const float*)d_in[0];   // [1M, 128]
    const float* adj_mean = (const float*)d_in[1];   // [1024, 1024]
    const float* W        = (const float*)d_in[2];   // [128, 64]
    const float* a        = (const float*)d_in[3];   // [64]
    const float* gamma1   = (const float*)d_in[4];
    const float* beta1    = (const float*)d_in[5];
    const float* gamma2   = (const float*)d_in[6];
    const float* beta2    = (const float*)d_in[7];
    const float* gamma3   = (const float*)d_in[8];
    const float* beta3    = (const float*)d_in[9];
    float* out            = (float*)d_out;

    k_zero<<<1, 128>>>();
    k_colstats<<<2048, 256>>>((const float4*)adj);
    k_fin1<<<1, 128>>>(W, gamma1, beta1);
    k_gemm<<<MROWS / 256, 256>>>(adj);
    k_fin2<<<1, 64>>>(gamma2, beta2);
    k_rowdot<<<2048, 256>>>(a);
    k_fin3<<<1, 1>>>(gamma3, beta3);
    k_softmax<<<NROW, 256>>>(adj_mean, out);
}

// round 6
// speedup vs baseline: 1.1563x; 1.1563x over previous
#include <cuda_runtime.h>

#define FIN   128
#define FHID  64
#define NROW  1024
#define MROWS (NROW*NROW)
#define EPSV  1e-5f
#define ALPHA 0.2f
#define NEGV  -9e15f

// GEMM tiling
#define TM     128          // rows per block
#define KC     16           // k-slice per stage
#define XPAD   20           // words per row in x smem (banks: r4*20 mod 32 distinct)
#define NSTAGE (FIN/KC)     // 8

// ---------------- scratch (device globals: no allocation allowed) ----------
__device__ float g_sum1[FIN],  g_sumsq1[FIN];
__device__ float g_Wp[FIN*FHID], g_bp[FHID];
__device__ float g_sum2[FHID], g_sumsq2[FHID];
__device__ float g_sc2[FHID],  g_bi2[FHID];
__device__ float g_s3[2];
__device__ float g_eaff[2];
__device__ float g_y[(size_t)MROWS*FHID];   // 256 MB scratch for pre-BN2 activations
__device__ float g_s[MROWS];                // 4 MB pre-BN3 scalars

// ---------------- packed f32x2 helpers (FFMA2 path, sm_100+) ---------------
__device__ __forceinline__ unsigned long long pack2(float lo, float hi) {
    unsigned long long r;
    asm("mov.b64 %0, {%1, %2};" : "=l"(r) : "f"(lo), "f"(hi));
    return r;
}
__device__ __forceinline__ float2 unpack2(unsigned long long v) {
    float2 f;
    asm("mov.b64 {%0, %1}, %2;" : "=f"(f.x), "=f"(f.y) : "l"(v));
    return f;
}
__device__ __forceinline__ unsigned long long ffma2(unsigned long long a,
                                                    unsigned long long b,
                                                    unsigned long long c) {
    unsigned long long d;
    asm("fma.rn.f32x2 %0, %1, %2, %3;" : "=l"(d) : "l"(a), "l"(b), "l"(c));
    return d;
}
__device__ __forceinline__ unsigned long long add2(unsigned long long a,
                                                   unsigned long long b) {
    unsigned long long d;
    asm("add.rn.f32x2 %0, %1, %2;" : "=l"(d) : "l"(a), "l"(b));
    return d;
}
__device__ __forceinline__ unsigned long long mul2(unsigned long long a,
                                                   unsigned long long b) {
    unsigned long long d;
    asm("mul.rn.f32x2 %0, %1, %2;" : "=l"(d) : "l"(a), "l"(b));
    return d;
}

__device__ __forceinline__ float leakyf(float v) { return v >= 0.f ? v : ALPHA * v; }

// ---------------- K0: zero accumulators ------------------------------------
__global__ void k_zero() {
    int t = threadIdx.x;  // 128 threads
    if (t < FIN)  { g_sum1[t] = 0.f; g_sumsq1[t] = 0.f; }
    if (t < FHID) { g_sum2[t] = 0.f; g_sumsq2[t] = 0.f; }
    if (t < 2)    { g_s3[t] = 0.f; }
}

// ---------------- K1: per-feature sum / sumsq over 1M rows ------------------
__global__ void k_colstats(const float4* __restrict__ x) {
    __shared__ float shS[8 * FIN], shQ[8 * FIN];
    int tid = threadIdx.x, lane = tid & 31, w = tid >> 5;  // 256 thr = 8 warps
    float4 s = make_float4(0.f, 0.f, 0.f, 0.f);
    float4 q = make_float4(0.f, 0.f, 0.f, 0.f);
    for (int r = blockIdx.x * 8 + w; r < MROWS; r += gridDim.x * 8) {
        float4 v = x[(size_t)r * (FIN / 4) + lane];
        s.x += v.x; s.y += v.y; s.z += v.z; s.w += v.w;
        q.x += v.x * v.x; q.y += v.y * v.y; q.z += v.z * v.z; q.w += v.w * v.w;
    }
    ((float4*)(shS + w * FIN))[lane] = s;
    ((float4*)(shQ + w * FIN))[lane] = q;
    __syncthreads();
    if (tid < FIN) {
        float a = 0.f, b = 0.f;
        #pragma unroll
        for (int ww = 0; ww < 8; ww++) { a += shS[ww * FIN + tid]; b += shQ[ww * FIN + tid]; }
        atomicAdd(&g_sum1[tid], a);
        atomicAdd(&g_sumsq1[tid], b);
    }
}

// ---------------- K2: fold BN1 into W --------------------------------------
__global__ void k_fin1(const float* __restrict__ W, const float* __restrict__ g1,
                       const float* __restrict__ b1) {
    __shared__ float s1[FIN], t1[FIN];
    int tid = threadIdx.x;  // 128
    float inv = 1.f / (float)MROWS;
    float mu  = g_sum1[tid] * inv;
    float var = g_sumsq1[tid] * inv - mu * mu;
    float rs  = rsqrtf(var + EPSV);
    float sc  = g1[tid] * rs;
    s1[tid] = sc;
    t1[tid] = b1[tid] - mu * sc;
    __syncthreads();
    float sv = s1[tid];
    for (int h = 0; h < FHID; h++) g_Wp[tid * FHID + h] = sv * W[tid * FHID + h];
    if (tid < FHID) {
        float acc = 0.f;
        for (int f = 0; f < FIN; f++) acc += t1[f] * W[f * FHID + tid];
        g_bp[tid] = acc;
    }
}

// ---------------- K3: register-blocked GEMM y = x@Wp + bp (+ y stats) -------
// 256 threads; block tile 128 rows x 64 cols; thread tile 4 rows x 8 cols.
// x and W both staged through double-buffered smem (cp.async).
// Total static smem ~29 KB -> no opt-in needed, 3+ blocks/SM.
__global__ __launch_bounds__(256) void k_gemm(const float* __restrict__ x) {
    __shared__ float xs[2 * TM * XPAD];              // 20 KB
    __shared__ float sWt[2 * KC * FHID];             // 8 KB
    __shared__ unsigned long long sBp[FHID / 2];
    __shared__ float sS[FHID], sQ[FHID];

    int tid = threadIdx.x, lane = tid & 31, warp = tid >> 5;
    int r4 = lane >> 3, c8 = lane & 7;
    int warpRow = warp * 16;                         // 8 warps x 16 rows

    if (tid < FHID / 2) sBp[tid] = pack2(g_bp[2 * tid], g_bp[2 * tid + 1]);
    if (tid < FHID) { sS[tid] = 0.f; sQ[tid] = 0.f; }

    size_t blockRow = (size_t)blockIdx.x * TM;
    const float* xg = x + blockRow * FIN;

    // stage loader: x 128 rows x 16 floats (2 float4/thread) + W 16x64 (64 float4)
    #define ISSUE_STAGE(S) do {                                                  \
        int _s = (S), _buf = _s & 1;                                             \
        _Pragma("unroll")                                                        \
        for (int _j = 0; _j < 2; _j++) {                                         \
            int _flat = _j * 256 + tid;                                          \
            int _row = _flat >> 2, _q = _flat & 3;                               \
            const float* _src = xg + (size_t)_row * FIN + _s * KC + _q * 4;      \
            unsigned _dst = (unsigned)__cvta_generic_to_shared(                  \
                &xs[(_buf * TM + _row) * XPAD + _q * 4]);                        \
            asm volatile("cp.async.ca.shared.global [%0], [%1], 16;"             \
                         :: "r"(_dst), "l"(_src));                               \
        }                                                                        \
        if (tid < KC * FHID / 4) {                                               \
            const float* _wsrc = g_Wp + _s * KC * FHID + tid * 4;                \
            unsigned _wdst = (unsigned)__cvta_generic_to_shared(                 \
                &sWt[_buf * KC * FHID + tid * 4]);                               \
            asm volatile("cp.async.ca.shared.global [%0], [%1], 16;"             \
                         :: "r"(_wdst), "l"(_wsrc));                             \
        }                                                                        \
        asm volatile("cp.async.commit_group;");                                  \
    } while (0)

    ISSUE_STAGE(0);
    ISSUE_STAGE(1);
    asm volatile("cp.async.wait_group 1;");
    __syncthreads();            // sBp, sS, sQ, stage0 visible

    unsigned long long acc[4][4];
    {
        unsigned long long b0 = sBp[c8 * 4 + 0], b1 = sBp[c8 * 4 + 1];
        unsigned long long b2 = sBp[c8 * 4 + 2], b3 = sBp[c8 * 4 + 3];
        #pragma unroll
        for (int i = 0; i < 4; i++) {
            acc[i][0] = b0; acc[i][1] = b1; acc[i][2] = b2; acc[i][3] = b3;
        }
    }

    for (int s = 0; s < NSTAGE; s++) {
        if (s) {
            if (s == NSTAGE - 1) asm volatile("cp.async.wait_group 0;");
            else                 asm volatile("cp.async.wait_group 1;");
            __syncthreads();
        }
        const float* xb = xs  + (s & 1) * TM * XPAD;
        const float* wb = sWt + (s & 1) * KC * FHID;
        #pragma unroll
        for (int k2 = 0; k2 < KC / 2; k2++) {
            int k = 2 * k2;
            const float* w0 = wb + k * FHID + c8 * 8;
            ulonglong2 w00 = *(const ulonglong2*)(w0);
            ulonglong2 w01 = *(const ulonglong2*)(w0 + 4);
            ulonglong2 w10 = *(const ulonglong2*)(w0 + FHID);
            ulonglong2 w11 = *(const ulonglong2*)(w0 + FHID + 4);
            float2 xr[4];
            #pragma unroll
            for (int i = 0; i < 4; i++)
                xr[i] = *(const float2*)&xb[(warpRow + r4 + 4 * i) * XPAD + k];
            #pragma unroll
            for (int i = 0; i < 4; i++) {
                unsigned long long xa = pack2(xr[i].x, xr[i].x);
                acc[i][0] = ffma2(xa, w00.x, acc[i][0]);
                acc[i][1] = ffma2(xa, w00.y, acc[i][1]);
                acc[i][2] = ffma2(xa, w01.x, acc[i][2]);
                acc[i][3] = ffma2(xa, w01.y, acc[i][3]);
                unsigned long long xc = pack2(xr[i].y, xr[i].y);
                acc[i][0] = ffma2(xc, w10.x, acc[i][0]);
                acc[i][1] = ffma2(xc, w10.y, acc[i][1]);
                acc[i][2] = ffma2(xc, w11.x, acc[i][2]);
                acc[i][3] = ffma2(xc, w11.y, acc[i][3]);
            }
        }
        __syncthreads();        // everyone done reading buffers before refill
        if (s + 2 < NSTAGE) ISSUE_STAGE(s + 2);
    }
    #undef ISSUE_STAGE

    // ---- write y (4 rows x 8 cols per thread) -------------------------------
    #pragma unroll
    for (int i = 0; i < 4; i++) {
        size_t row = blockRow + warpRow + r4 + 4 * i;
        ulonglong2 v0; v0.x = acc[i][0]; v0.y = acc[i][1];
        ulonglong2 v1; v1.x = acc[i][2]; v1.y = acc[i][3];
        *(ulonglong2*)&g_y[row * FHID + c8 * 8]     = v0;
        *(ulonglong2*)&g_y[row * FHID + c8 * 8 + 4] = v1;
    }

    // ---- BN2 stats: thread-local row sum, r4-shuffle, shared+global atomics -
    unsigned long long ps[4], pq[4];
    #pragma unroll
    for (int j = 0; j < 4; j++) {
        unsigned long long vs = acc[0][j];
        unsigned long long vq = mul2(acc[0][j], acc[0][j]);
        #pragma unroll
        for (int i = 1; i < 4; i++) {
            vs = add2(vs, acc[i][j]);
            vq = add2(vq, mul2(acc[i][j], acc[i][j]));
        }
        ps[j] = vs; pq[j] = vq;
    }
    #pragma unroll
    for (int j = 0; j < 4; j++) {
        ps[j] = add2(ps[j], __shfl_xor_sync(0xffffffffu, ps[j], 8));
        ps[j] = add2(ps[j], __shfl_xor_sync(0xffffffffu, ps[j], 16));
        pq[j] = add2(pq[j], __shfl_xor_sync(0xffffffffu, pq[j], 8));
        pq[j] = add2(pq[j], __shfl_xor_sync(0xffffffffu, pq[j], 16));
    }
    if (r4 == 0) {
        #pragma unroll
        for (int j = 0; j < 4; j++) {
            float2 s2 = unpack2(ps[j]), q2 = unpack2(pq[j]);
            atomicAdd(&sS[c8 * 8 + 2 * j],     s2.x);
            atomicAdd(&sS[c8 * 8 + 2 * j + 1], s2.y);
            atomicAdd(&sQ[c8 * 8 + 2 * j],     q2.x);
            atomicAdd(&sQ[c8 * 8 + 2 * j + 1], q2.y);
        }
    }
    __syncthreads();
    if (tid < FHID) {
        atomicAdd(&g_sum2[tid], sS[tid]);
        atomicAdd(&g_sumsq2[tid], sQ[tid]);
    }
}

// ---------------- K4: finalize BN2 affine ----------------------------------
__global__ void k_fin2(const float* __restrict__ g2, const float* __restrict__ b2) {
    int tid = threadIdx.x;  // 64
    float inv = 1.f / (float)MROWS;
    float mu  = g_sum2[tid] * inv;
    float var = g_sumsq2[tid] * inv - mu * mu;
    float rs  = rsqrtf(var + EPSV);
    float sc  = g2[tid] * rs;
    g_sc2[tid] = sc;
    g_bi2[tid] = b2[tid] - mu * sc;
}

// ---------------- K5: s = leaky(bn2(y)) @ a  (+ s stats) --------------------
__global__ void k_rowdot(const float* __restrict__ a_vec) {
    __shared__ float sc[FHID], sb[FHID], sa[FHID];
    __shared__ float redS[8], redQ[8];
    int tid = threadIdx.x, lane = tid & 31, w = tid >> 5;  // 256 thr
    if (tid < FHID) { sc[tid] = g_sc2[tid]; sb[tid] = g_bi2[tid]; sa[tid] = a_vec[tid]; }
    __syncthreads();
    int h0 = 2 * lane, h1 = h0 + 1;
    float c0 = sc[h0], b0 = sb[h0], A0 = sa[h0];
    float c1 = sc[h1], b1 = sb[h1], A1 = sa[h1];
    float ps = 0.f, pq = 0.f;
    for (int r = blockIdx.x * 8 + w; r < MROWS; r += gridDim.x * 8) {
        float2 v = ((const float2*)(g_y + (size_t)r * FHID))[lane];
        float z0 = leakyf(v.x * c0 + b0);
        float z1 = leakyf(v.y * c1 + b1);
        float t  = A0 * z0 + A1 * z1;
        #pragma unroll
        for (int o = 16; o; o >>= 1) t += __shfl_xor_sync(0xffffffffu, t, o);
        if (lane == 0) { g_s[r] = t; ps += t; pq += t * t; }
    }
    if (lane == 0) { redS[w] = ps; redQ[w] = pq; }
    __syncthreads();
    if (tid == 0) {
        float S = 0.f, Q = 0.f;
        #pragma unroll
        for (int i = 0; i < 8; i++) { S += redS[i]; Q += redQ[i]; }
        atomicAdd(&g_s3[0], S);
        atomicAdd(&g_s3[1], Q);
    }
}

// ---------------- K6: finalize BN3 affine ----------------------------------
__global__ void k_fin3(const float* __restrict__ g3, const float* __restrict__ b3) {
    float inv = 1.f / (float)MROWS;
    float mu  = g_s3[0] * inv;
    float var = g_s3[1] * inv - mu * mu;
    float rs  = rsqrtf(var + EPSV);
    float c   = g3[0] * rs;
    g_eaff[0] = c;
    g_eaff[1] = b3[0] - mu * c;
}

// ---------------- K7: masked row softmax ------------------------------------
__global__ void k_softmax(const float* __restrict__ adj_mean, float* __restrict__ out) {
    __shared__ float redm[8], reds[8];
    int row = blockIdx.x, tid = threadIdx.x, lane = tid & 31, w = tid >> 5;  // 256 thr
    float c3 = g_eaff[0], d3 = g_eaff[1];
    const float4* sp = (const float4*)(g_s + (size_t)row * NROW);
    const float4* mp = (const float4*)(adj_mean + (size_t)row * NROW);
    float4 sv = sp[tid];
    float4 mv = mp[tid];
    float v0 = (mv.x > 0.f) ? leakyf(sv.x * c3 + d3) : NEGV;
    float v1 = (mv.y > 0.f) ? leakyf(sv.y * c3 + d3) : NEGV;
    float v2 = (mv.z > 0.f) ? leakyf(sv.z * c3 + d3) : NEGV;
    float v3 = (mv.w > 0.f) ? leakyf(sv.w * c3 + d3) : NEGV;

    float m = fmaxf(fmaxf(v0, v1), fmaxf(v2, v3));
    #pragma unroll
    for (int o = 16; o; o >>= 1) m = fmaxf(m, __shfl_xor_sync(0xffffffffu, m, o));
    if (lane == 0) redm[w] = m;
    __syncthreads();
    if (tid < 8) {
        float t = redm[tid];
        #pragma unroll
        for (int o = 4; o; o >>= 1) t = fmaxf(t, __shfl_xor_sync(0xffu, t, o));
        if (tid == 0) redm[0] = t;
    }
    __syncthreads();
    float rm = redm[0];

    float p0 = expf(v0 - rm), p1 = expf(v1 - rm), p2 = expf(v2 - rm), p3 = expf(v3 - rm);
    float s = p0 + p1 + p2 + p3;
    #pragma unroll
    for (int o = 16; o; o >>= 1) s += __shfl_xor_sync(0xffffffffu, s, o);
    if (lane == 0) reds[w] = s;
    __syncthreads();
    if (tid < 8) {
        float t = reds[tid];
        #pragma unroll
        for (int o = 4; o; o >>= 1) t += __shfl_xor_sync(0xffu, t, o);
        if (tid == 0) reds[0] = t;
    }
    __syncthreads();
    float invs = 1.f / reds[0];

    ((float4*)(out + (size_t)row * NROW))[tid] =
        make_float4(p0 * invs, p1 * invs, p2 * invs, p3 * invs);
}

// ---------------- launcher ---------------------------------------------------
extern "C" void kernel_launch(void* const* d_in, const int* in_sizes, int n_in,
                              void* d_out, int out_size) {
    const float* adj      = (const float*)d_in[0];   // [1M, 128]
    const float* adj_mean = (const float*)d_in[1];   // [1024, 1024]
    const float* W        = (const float*)d_in[2];   // [128, 64]
    const float* a        = (const float*)d_in[3];   // [64]
    const float* gamma1   = (const float*)d_in[4];
    const float* beta1    = (const float*)d_in[5];
    const float* gamma2   = (const float*)d_in[6];
    const float* beta2    = (const float*)d_in[7];
    const float* gamma3   = (const float*)d_in[8];
    const float* beta3    = (const float*)d_in[9];
    float* out            = (float*)d_out;

    k_zero<<<1, 128>>>();
    k_colstats<<<2048, 256>>>((const float4*)adj);
    k_fin1<<<1, 128>>>(W, gamma1, beta1);
    k_gemm<<<MROWS / TM, 256>>>(adj);
    k_fin2<<<1, 64>>>(gamma2, beta2);
    k_rowdot<<<2048, 256>>>(a);
    k_fin3<<<1, 1>>>(gamma3, beta3);
    k_softmax<<<NROW, 256>>>(adj_mean, out);
}

// round 8
// speedup vs baseline: 2.1197x; 1.8333x over previous
#include <cuda_runtime.h>
#include <cuda_bf16.h>
#include <cstdint>

#define FIN   128
#define FHID  64
#define NROW  1024
#define MROWS (NROW*NROW)
#define EPSV  1e-5f
#define ALPHA 0.2f
#define NEGV  -9e15f

#define GTM     128          // rows per GEMM CTA
#define WSTRIDE 68           // words per W-row in smem (68 mod 32 = 4 -> conflict-free)

// ---------------- scratch ----------------------------------------------------
__device__ float g_sum1[FIN],  g_sumsq1[FIN];
__device__ float g_bp[FHID];
__device__ __nv_bfloat16 g_WpT_hi[FHID*FIN];   // [n][k] K-major
__device__ __nv_bfloat16 g_WpT_lo[FHID*FIN];
__device__ float g_sum2[FHID], g_sumsq2[FHID];
__device__ float g_sc2[FHID],  g_bi2[FHID];
__device__ float g_s3[2];
__device__ float g_eaff[2];
__device__ float g_y[(size_t)MROWS*FHID];      // 256 MB pre-BN2 activations
__device__ float g_s[MROWS];                   // 4 MB pre-BN3 scalars

// ---------------- helpers ----------------------------------------------------
__device__ __forceinline__ unsigned long long pack2(float lo, float hi) {
    unsigned long long r;
    asm("mov.b64 %0, {%1, %2};" : "=l"(r) : "f"(lo), "f"(hi));
    return r;
}
__device__ __forceinline__ float2 unpack2(unsigned long long v) {
    float2 f;
    asm("mov.b64 {%0, %1}, %2;" : "=f"(f.x), "=f"(f.y) : "l"(v));
    return f;
}
__device__ __forceinline__ unsigned long long add2(unsigned long long a,
                                                   unsigned long long b) {
    unsigned long long d;
    asm("add.rn.f32x2 %0, %1, %2;" : "=l"(d) : "l"(a), "l"(b));
    return d;
}
__device__ __forceinline__ float leakyf(float v) { return v >= 0.f ? v : ALPHA * v; }

// bf16x2 pack: low half <- a, high half <- b
__device__ __forceinline__ uint32_t bf16x2_of(float a, float b) {
    uint32_t d;
    asm("cvt.rn.bf16x2.f32 %0, %1, %2;" : "=r"(d) : "f"(b), "f"(a));
    return d;
}
__device__ __forceinline__ float bf16lo_f(uint32_t w) { return __uint_as_float(w << 16); }
__device__ __forceinline__ float bf16hi_f(uint32_t w) { return __uint_as_float(w & 0xFFFF0000u); }

// m16n8k16 row.col bf16 -> f32 accumulate-in-place
#define MMA16816(c, a0, a1, a2, a3, b0, b1)                                       \
    asm volatile("mma.sync.aligned.m16n8k16.row.col.f32.bf16.bf16.f32 "           \
                 "{%0,%1,%2,%3}, {%4,%5,%6,%7}, {%8,%9}, {%0,%1,%2,%3};"          \
                 : "+f"((c)[0]), "+f"((c)[1]), "+f"((c)[2]), "+f"((c)[3])         \
                 : "r"(a0), "r"(a1), "r"(a2), "r"(a3), "r"(b0), "r"(b1))

// ---------------- K0: zero accumulators ------------------------------------
__global__ void k_zero() {
    int t = threadIdx.x;  // 128 threads
    if (t < FIN)  { g_sum1[t] = 0.f; g_sumsq1[t] = 0.f; }
    if (t < FHID) { g_sum2[t] = 0.f; g_sumsq2[t] = 0.f; }
    if (t < 2)    { g_s3[t] = 0.f; }
}

// ---------------- K1: per-feature sum / sumsq over 1M rows ------------------
__global__ void k_colstats(const float4* __restrict__ x) {
    __shared__ float shS[8 * FIN], shQ[8 * FIN];
    int tid = threadIdx.x, lane = tid & 31, w = tid >> 5;
    float4 s = make_float4(0.f, 0.f, 0.f, 0.f);
    float4 q = make_float4(0.f, 0.f, 0.f, 0.f);
    for (int r = blockIdx.x * 8 + w; r < MROWS; r += gridDim.x * 8) {
        float4 v = x[(size_t)r * (FIN / 4) + lane];
        s.x += v.x; s.y += v.y; s.z += v.z; s.w += v.w;
        q.x += v.x * v.x; q.y += v.y * v.y; q.z += v.z * v.z; q.w += v.w * v.w;
    }
    ((float4*)(shS + w * FIN))[lane] = s;
    ((float4*)(shQ + w * FIN))[lane] = q;
    __syncthreads();
    if (tid < FIN) {
        float a = 0.f, b = 0.f;
        #pragma unroll
        for (int ww = 0; ww < 8; ww++) { a += shS[ww * FIN + tid]; b += shQ[ww * FIN + tid]; }
        atomicAdd(&g_sum1[tid], a);
        atomicAdd(&g_sumsq1[tid], b);
    }
}

// ---------------- K2: fold BN1 into W; emit bf16-split W^T ------------------
__global__ void k_fin1(const float* __restrict__ W, const float* __restrict__ g1,
                       const float* __restrict__ b1) {
    __shared__ float s1[FIN], t1[FIN];
    int tid = threadIdx.x;  // 128 threads, tid = k
    float inv = 1.f / (float)MROWS;
    float mu  = g_sum1[tid] * inv;
    float var = g_sumsq1[tid] * inv - mu * mu;
    float rs  = rsqrtf(var + EPSV);
    float sc  = g1[tid] * rs;
    s1[tid] = sc;
    t1[tid] = b1[tid] - mu * sc;
    __syncthreads();
    float sv = s1[tid];
    for (int n = 0; n < FHID; n++) {
        float wv = sv * W[tid * FHID + n];
        __nv_bfloat16 bh = __float2bfloat16_rn(wv);
        float bhf = __bfloat162float(bh);
        __nv_bfloat16 bl = __float2bfloat16_rn(wv - bhf);
        g_WpT_hi[n * FIN + tid] = bh;
        g_WpT_lo[n * FIN + tid] = bl;
    }
    if (tid < FHID) {
        float acc = 0.f;
        for (int f = 0; f < FIN; f++) acc += t1[f] * W[f * FHID + tid];
        g_bp[tid] = acc;
    }
}

// ---------------- K3: mma.sync GEMM  y = x@Wp + bp  (+ y stats) -------------
// 256 thr / 8 warps; CTA tile 128x64; warp tile 16x64.
// A: fp32 from gmem -> bf16 hi/lo fragments in regs (x read once, no smem).
// B: W^T hi/lo resident in padded smem rows (conflict-free 4B loads).
// 3 passes: Ah*Bh + Al*Bh + Ah*Bl into one fp32 accumulator.
__global__ __launch_bounds__(256) void k_gemm_mma(const float* __restrict__ x) {
    __shared__ uint32_t sWh[FHID * WSTRIDE], sWl[FHID * WSTRIDE];
    __shared__ float sS[FHID], sQ[FHID], sBp[FHID];

    int tid = threadIdx.x, lane = tid & 31, wid = tid >> 5;
    int gid = lane >> 2, tig = lane & 3;

    // fill W smem: 64 rows x 64 words (128 bf16), padded stride WSTRIDE
    for (int i = tid; i < FHID * (FIN / 2); i += 256) {
        int n = i >> 6, w = i & 63;
        sWh[n * WSTRIDE + w] = ((const uint32_t*)g_WpT_hi)[n * (FIN / 2) + w];
        sWl[n * WSTRIDE + w] = ((const uint32_t*)g_WpT_lo)[n * (FIN / 2) + w];
    }
    if (tid < FHID) { sS[tid] = 0.f; sQ[tid] = 0.f; sBp[tid] = g_bp[tid]; }
    __syncthreads();

    size_t blockRow = (size_t)blockIdx.x * GTM;
    size_t row0 = blockRow + 16 * wid + gid;          // fragment rows: row0, row0+8
    const float* xr0 = x + row0 * FIN;
    const float* xr1 = x + (row0 + 8) * FIN;

    float acc[8][4];
    #pragma unroll
    for (int nt = 0; nt < 8; nt++)
        { acc[nt][0] = 0.f; acc[nt][1] = 0.f; acc[nt][2] = 0.f; acc[nt][3] = 0.f; }

    #pragma unroll
    for (int kt = 0; kt < 8; kt++) {
        int k0 = 16 * kt + 2 * tig;
        float2 v00 = *(const float2*)(xr0 + k0);       // row gid,   k, k+1
        float2 v10 = *(const float2*)(xr1 + k0);       // row gid+8
        float2 v01 = *(const float2*)(xr0 + k0 + 8);   // row gid,   k+8
        float2 v11 = *(const float2*)(xr1 + k0 + 8);

        uint32_t ah0 = bf16x2_of(v00.x, v00.y);
        uint32_t ah1 = bf16x2_of(v10.x, v10.y);
        uint32_t ah2 = bf16x2_of(v01.x, v01.y);
        uint32_t ah3 = bf16x2_of(v11.x, v11.y);
        uint32_t al0 = bf16x2_of(v00.x - bf16lo_f(ah0), v00.y - bf16hi_f(ah0));
        uint32_t al1 = bf16x2_of(v10.x - bf16lo_f(ah1), v10.y - bf16hi_f(ah1));
        uint32_t al2 = bf16x2_of(v01.x - bf16lo_f(ah2), v01.y - bf16hi_f(ah2));
        uint32_t al3 = bf16x2_of(v11.x - bf16lo_f(ah3), v11.y - bf16hi_f(ah3));

        const uint32_t* wh = &sWh[gid * WSTRIDE + 8 * kt + tig];
        const uint32_t* wl = &sWl[gid * WSTRIDE + 8 * kt + tig];
        #pragma unroll
        for (int nt = 0; nt < 8; nt++) {
            uint32_t bh0 = wh[nt * 8 * WSTRIDE];
            uint32_t bh1 = wh[nt * 8 * WSTRIDE + 4];
            uint32_t bl0 = wl[nt * 8 * WSTRIDE];
            uint32_t bl1 = wl[nt * 8 * WSTRIDE + 4];
            MMA16816(acc[nt], ah0, ah1, ah2, ah3, bh0, bh1);
            MMA16816(acc[nt], al0, al1, al2, al3, bh0, bh1);
            MMA16816(acc[nt], ah0, ah1, ah2, ah3, bl0, bl1);
        }
    }

    // ---- epilogue: bias, store y, BN2 stats ---------------------------------
    #pragma unroll
    for (int nt = 0; nt < 8; nt++) {
        int col = 8 * nt + 2 * tig;
        float b0 = sBp[col], b1 = sBp[col + 1];
        float c0 = acc[nt][0] + b0, c1 = acc[nt][1] + b1;
        float c2 = acc[nt][2] + b0, c3 = acc[nt][3] + b1;
        *(float2*)&g_y[row0 * FHID + col]       = make_float2(c0, c1);
        *(float2*)&g_y[(row0 + 8) * FHID + col] = make_float2(c2, c3);

        unsigned long long vs = pack2(c0 + c2, c1 + c3);
        unsigned long long vq = pack2(c0 * c0 + c2 * c2, c1 * c1 + c3 * c3);
        #pragma unroll
        for (int o = 4; o <= 16; o <<= 1) {           // reduce across gid bits
            vs = add2(vs, __shfl_xor_sync(0xffffffffu, vs, o));
            vq = add2(vq, __shfl_xor_sync(0xffffffffu, vq, o));
        }
        if (gid == 0) {
            float2 s2 = unpack2(vs), q2 = unpack2(vq);
            atomicAdd(&sS[col],     s2.x);
            atomicAdd(&sS[col + 1], s2.y);
            atomicAdd(&sQ[col],     q2.x);
            atomicAdd(&sQ[col + 1], q2.y);
        }
    }
    __syncthreads();
    if (tid < FHID) {
        atomicAdd(&g_sum2[tid], sS[tid]);
        atomicAdd(&g_sumsq2[tid], sQ[tid]);
    }
}

// ---------------- K4: finalize BN2 affine ----------------------------------
__global__ void k_fin2(const float* __restrict__ g2, const float* __restrict__ b2) {
    int tid = threadIdx.x;  // 64
    float inv = 1.f / (float)MROWS;
    float mu  = g_sum2[tid] * inv;
    float var = g_sumsq2[tid] * inv - mu * mu;
    float rs  = rsqrtf(var + EPSV);
    float sc  = g2[tid] * rs;
    g_sc2[tid] = sc;
    g_bi2[tid] = b2[tid] - mu * sc;
}

// ---------------- K5: s = leaky(bn2(y)) @ a  (+ s stats) --------------------
__global__ void k_rowdot(const float* __restrict__ a_vec) {
    __shared__ float sc[FHID], sb[FHID], sa[FHID];
    __shared__ float redS[8], redQ[8];
    int tid = threadIdx.x, lane = tid & 31, w = tid >> 5;  // 256 thr
    if (tid < FHID) { sc[tid] = g_sc2[tid]; sb[tid] = g_bi2[tid]; sa[tid] = a_vec[tid]; }
    __syncthreads();
    int h0 = 2 * lane, h1 = h0 + 1;
    float c0 = sc[h0], b0 = sb[h0], A0 = sa[h0];
    float c1 = sc[h1], b1 = sb[h1], A1 = sa[h1];
    float ps = 0.f, pq = 0.f;
    for (int r = blockIdx.x * 8 + w; r < MROWS; r += gridDim.x * 8) {
        float2 v = ((const float2*)(g_y + (size_t)r * FHID))[lane];
        float z0 = leakyf(v.x * c0 + b0);
        float z1 = leakyf(v.y * c1 + b1);
        float t  = A0 * z0 + A1 * z1;
        #pragma unroll
        for (int o = 16; o; o >>= 1) t += __shfl_xor_sync(0xffffffffu, t, o);
        if (lane == 0) { g_s[r] = t; ps += t; pq += t * t; }
    }
    if (lane == 0) { redS[w] = ps; redQ[w] = pq; }
    __syncthreads();
    if (tid == 0) {
        float S = 0.f, Q = 0.f;
        #pragma unroll
        for (int i = 0; i < 8; i++) { S += redS[i]; Q += redQ[i]; }
        atomicAdd(&g_s3[0], S);
        atomicAdd(&g_s3[1], Q);
    }
}

// ---------------- K6: finalize BN3 affine ----------------------------------
__global__ void k_fin3(const float* __restrict__ g3, const float* __restrict__ b3) {
    float inv = 1.f / (float)MROWS;
    float mu  = g_s3[0] * inv;
    float var = g_s3[1] * inv - mu * mu;
    float rs  = rsqrtf(var + EPSV);
    float c   = g3[0] * rs;
    g_eaff[0] = c;
    g_eaff[1] = b3[0] - mu * c;
}

// ---------------- K7: masked row softmax ------------------------------------
__global__ void k_softmax(const float* __restrict__ adj_mean, float* __restrict__ out) {
    __shared__ float redm[8], reds[8];
    int row = blockIdx.x, tid = threadIdx.x, lane = tid & 31, w = tid >> 5;
    float c3 = g_eaff[0], d3 = g_eaff[1];
    float4 sv = ((const float4*)(g_s + (size_t)row * NROW))[tid];
    float4 mv = ((const float4*)(adj_mean + (size_t)row * NROW))[tid];
    float v0 = (mv.x > 0.f) ? leakyf(sv.x * c3 + d3) : NEGV;
    float v1 = (mv.y > 0.f) ? leakyf(sv.y * c3 + d3) : NEGV;
    float v2 = (mv.z > 0.f) ? leakyf(sv.z * c3 + d3) : NEGV;
    float v3 = (mv.w > 0.f) ? leakyf(sv.w * c3 + d3) : NEGV;

    float m = fmaxf(fmaxf(v0, v1), fmaxf(v2, v3));
    #pragma unroll
    for (int o = 16; o; o >>= 1) m = fmaxf(m, __shfl_xor_sync(0xffffffffu, m, o));
    if (lane == 0) redm[w] = m;
    __syncthreads();
    if (tid < 8) {
        float t = redm[tid];
        #pragma unroll
        for (int o = 4; o; o >>= 1) t = fmaxf(t, __shfl_xor_sync(0xffu, t, o));
        if (tid == 0) redm[0] = t;
    }
    __syncthreads();
    float rm = redm[0];

    float p0 = expf(v0 - rm), p1 = expf(v1 - rm), p2 = expf(v2 - rm), p3 = expf(v3 - rm);
    float s = p0 + p1 + p2 + p3;
    #pragma unroll
    for (int o = 16; o; o >>= 1) s += __shfl_xor_sync(0xffffffffu, s, o);
    if (lane == 0) reds[w] = s;
    __syncthreads();
    if (tid < 8) {
        float t = reds[tid];
        #pragma unroll
        for (int o = 4; o; o >>= 1) t += __shfl_xor_sync(0xffu, t, o);
        if (tid == 0) reds[0] = t;
    }
    __syncthreads();
    float invs = 1.f / reds[0];

    ((float4*)(out + (size_t)row * NROW))[tid] =
        make_float4(p0 * invs, p1 * invs, p2 * invs, p3 * invs);
}

// ---------------- launcher ---------------------------------------------------
extern "C" void kernel_launch(void* const* d_in, const int* in_sizes, int n_in,
                              void* d_out, int out_size) {
    const float* adj      = (const float*)d_in[0];
    const float* adj_mean = (const float*)d_in[1];
    const float* W        = (const float*)d_in[2];
    const float* a        = (const float*)d_in[3];
    const float* gamma1   = (const float*)d_in[4];
    const float* beta1    = (const float*)d_in[5];
    const float* gamma2   = (const float*)d_in[6];
    const float* beta2    = (const float*)d_in[7];
    const float* gamma3   = (const float*)d_in[8];
    const float* beta3    = (const float*)d_in[9];
    float* out            = (float*)d_out;

    k_zero<<<1, 128>>>();
    k_colstats<<<2048, 256>>>((const float4*)adj);
    k_fin1<<<1, 128>>>(W, gamma1, beta1);
    k_gemm_mma<<<MROWS / GTM, 256>>>(adj);
    k_fin2<<<1, 64>>>(gamma2, beta2);
    k_rowdot<<<2048, 256>>>(a);
    k_fin3<<<1, 1>>>(gamma3, beta3);
    k_softmax<<<NROW, 256>>>(adj_mean, out);
}

// round 9
// speedup vs baseline: 2.4836x; 1.1717x over previous
#include <cuda_runtime.h>
#include <cuda_bf16.h>
#include <cstdint>

#define FIN   128
#define FHID  64
#define NROW  1024
#define MROWS (NROW*NROW)
#define EPSV  1e-5f
#define ALPHA 0.2f
#define NEGV  -9e15f

#define GTM     256          // rows per GEMM CTA (8 warps x 32-row tiles)
#define WSTRIDE 68           // words per W-row in smem (68 mod 32 = 4 -> conflict-free)

// ---------------- scratch ----------------------------------------------------
__device__ float g_sum1[FIN],  g_sumsq1[FIN];
__device__ float g_bp[FHID];
__device__ __nv_bfloat16 g_WpT_hi[FHID*FIN];   // [n][k] K-major
__device__ __nv_bfloat16 g_WpT_lo[FHID*FIN];
__device__ float g_sum2[FHID], g_sumsq2[FHID];
__device__ float g_sc2[FHID],  g_bi2[FHID];
__device__ float g_s3[2];
__device__ float g_eaff[2];
__device__ float g_y[(size_t)MROWS*FHID];      // 256 MB pre-BN2 activations
__device__ float g_s[MROWS];                   // 4 MB pre-BN3 scalars

// ---------------- helpers ----------------------------------------------------
__device__ __forceinline__ unsigned long long pack2(float lo, float hi) {
    unsigned long long r;
    asm("mov.b64 %0, {%1, %2};" : "=l"(r) : "f"(lo), "f"(hi));
    return r;
}
__device__ __forceinline__ float2 unpack2(unsigned long long v) {
    float2 f;
    asm("mov.b64 {%0, %1}, %2;" : "=f"(f.x), "=f"(f.y) : "l"(v));
    return f;
}
__device__ __forceinline__ unsigned long long add2(unsigned long long a,
                                                   unsigned long long b) {
    unsigned long long d;
    asm("add.rn.f32x2 %0, %1, %2;" : "=l"(d) : "l"(a), "l"(b));
    return d;
}
__device__ __forceinline__ float leakyf(float v) { return v >= 0.f ? v : ALPHA * v; }

// bf16x2 pack: low half <- a, high half <- b
__device__ __forceinline__ uint32_t bf16x2_of(float a, float b) {
    uint32_t d;
    asm("cvt.rn.bf16x2.f32 %0, %1, %2;" : "=r"(d) : "f"(b), "f"(a));
    return d;
}
__device__ __forceinline__ float bf16lo_f(uint32_t w) { return __uint_as_float(w << 16); }
__device__ __forceinline__ float bf16hi_f(uint32_t w) { return __uint_as_float(w & 0xFFFF0000u); }

// m16n8k16 row.col bf16 -> f32 accumulate-in-place
#define MMA16816(c, a0, a1, a2, a3, b0, b1)                                       \
    asm volatile("mma.sync.aligned.m16n8k16.row.col.f32.bf16.bf16.f32 "           \
                 "{%0,%1,%2,%3}, {%4,%5,%6,%7}, {%8,%9}, {%0,%1,%2,%3};"          \
                 : "+f"((c)[0]), "+f"((c)[1]), "+f"((c)[2]), "+f"((c)[3])         \
                 : "r"(a0), "r"(a1), "r"(a2), "r"(a3), "r"(b0), "r"(b1))

// ---------------- K0: zero accumulators ------------------------------------
__global__ void k_zero() {
    int t = threadIdx.x;  // 128 threads
    if (t < FIN)  { g_sum1[t] = 0.f; g_sumsq1[t] = 0.f; }
    if (t < FHID) { g_sum2[t] = 0.f; g_sumsq2[t] = 0.f; }
    if (t < 2)    { g_s3[t] = 0.f; }
}

// ---------------- K1: per-feature sum / sumsq over 1M rows ------------------
__global__ void k_colstats(const float4* __restrict__ x) {
    __shared__ float shS[8 * FIN], shQ[8 * FIN];
    int tid = threadIdx.x, lane = tid & 31, w = tid >> 5;
    float4 s = make_float4(0.f, 0.f, 0.f, 0.f);
    float4 q = make_float4(0.f, 0.f, 0.f, 0.f);
    for (int r = blockIdx.x * 8 + w; r < MROWS; r += gridDim.x * 8) {
        float4 v = x[(size_t)r * (FIN / 4) + lane];
        s.x += v.x; s.y += v.y; s.z += v.z; s.w += v.w;
        q.x += v.x * v.x; q.y += v.y * v.y; q.z += v.z * v.z; q.w += v.w * v.w;
    }
    ((float4*)(shS + w * FIN))[lane] = s;
    ((float4*)(shQ + w * FIN))[lane] = q;
    __syncthreads();
    if (tid < FIN) {
        float a = 0.f, b = 0.f;
        #pragma unroll
        for (int ww = 0; ww < 8; ww++) { a += shS[ww * FIN + tid]; b += shQ[ww * FIN + tid]; }
        atomicAdd(&g_sum1[tid], a);
        atomicAdd(&g_sumsq1[tid], b);
    }
}

// ---------------- K2: fold BN1 into W; emit bf16-split W^T ------------------
__global__ void k_fin1(const float* __restrict__ W, const float* __restrict__ g1,
                       const float* __restrict__ b1) {
    __shared__ float s1[FIN], t1[FIN];
    int tid = threadIdx.x;  // 128 threads, tid = k
    float inv = 1.f / (float)MROWS;
    float mu  = g_sum1[tid] * inv;
    float var = g_sumsq1[tid] * inv - mu * mu;
    float rs  = rsqrtf(var + EPSV);
    float sc  = g1[tid] * rs;
    s1[tid] = sc;
    t1[tid] = b1[tid] - mu * sc;
    __syncthreads();
    float sv = s1[tid];
    for (int n = 0; n < FHID; n++) {
        float wv = sv * W[tid * FHID + n];
        __nv_bfloat16 bh = __float2bfloat16_rn(wv);
        float bhf = __bfloat162float(bh);
        __nv_bfloat16 bl = __float2bfloat16_rn(wv - bhf);
        g_WpT_hi[n * FIN + tid] = bh;
        g_WpT_lo[n * FIN + tid] = bl;
    }
    if (tid < FHID) {
        float acc = 0.f;
        for (int f = 0; f < FIN; f++) acc += t1[f] * W[f * FHID + tid];
        g_bp[tid] = acc;
    }
}

// ---------------- K3: mma.sync GEMM  y = x@Wp + bp  (+ y stats) -------------
// 256 thr / 8 warps; CTA tile 256x64; warp tile 32x64 (2 m-tiles).
// B-fragments loaded once per (nt,kt), reused across both m-tiles -> halves
// the per-row W smem traffic vs 16-row warp tiles.
__global__ __launch_bounds__(256, 2) void k_gemm_mma(const float* __restrict__ x) {
    __shared__ uint32_t sWh[FHID * WSTRIDE], sWl[FHID * WSTRIDE];
    __shared__ float sS[FHID], sQ[FHID], sBp[FHID];

    int tid = threadIdx.x, lane = tid & 31, wid = tid >> 5;
    int gid = lane >> 2, tig = lane & 3;

    for (int i = tid; i < FHID * (FIN / 2); i += 256) {
        int n = i >> 6, w = i & 63;
        sWh[n * WSTRIDE + w] = ((const uint32_t*)g_WpT_hi)[n * (FIN / 2) + w];
        sWl[n * WSTRIDE + w] = ((const uint32_t*)g_WpT_lo)[n * (FIN / 2) + w];
    }
    if (tid < FHID) { sS[tid] = 0.f; sQ[tid] = 0.f; sBp[tid] = g_bp[tid]; }
    __syncthreads();

    size_t blockRow = (size_t)blockIdx.x * GTM;
    size_t row0 = blockRow + 32 * wid + gid;           // rows: row0, +8, +16, +24
    const float* xr0 = x + row0 * FIN;
    const float* xr1 = x + (row0 + 8) * FIN;
    const float* xr2 = x + (row0 + 16) * FIN;
    const float* xr3 = x + (row0 + 24) * FIN;

    float acc[2][8][4];
    #pragma unroll
    for (int m = 0; m < 2; m++)
        #pragma unroll
        for (int nt = 0; nt < 8; nt++)
            #pragma unroll
            for (int j = 0; j < 4; j++) acc[m][nt][j] = 0.f;

    #pragma unroll
    for (int kt = 0; kt < 8; kt++) {
        int k0 = 16 * kt + 2 * tig;
        float2 v00 = *(const float2*)(xr0 + k0);
        float2 v10 = *(const float2*)(xr1 + k0);
        float2 v20 = *(const float2*)(xr2 + k0);
        float2 v30 = *(const float2*)(xr3 + k0);
        float2 v01 = *(const float2*)(xr0 + k0 + 8);
        float2 v11 = *(const float2*)(xr1 + k0 + 8);
        float2 v21 = *(const float2*)(xr2 + k0 + 8);
        float2 v31 = *(const float2*)(xr3 + k0 + 8);

        uint32_t ah0 = bf16x2_of(v00.x, v00.y);
        uint32_t ah1 = bf16x2_of(v10.x, v10.y);
        uint32_t ah2 = bf16x2_of(v01.x, v01.y);
        uint32_t ah3 = bf16x2_of(v11.x, v11.y);
        uint32_t ah4 = bf16x2_of(v20.x, v20.y);
        uint32_t ah5 = bf16x2_of(v30.x, v30.y);
        uint32_t ah6 = bf16x2_of(v21.x, v21.y);
        uint32_t ah7 = bf16x2_of(v31.x, v31.y);
        uint32_t al0 = bf16x2_of(v00.x - bf16lo_f(ah0), v00.y - bf16hi_f(ah0));
        uint32_t al1 = bf16x2_of(v10.x - bf16lo_f(ah1), v10.y - bf16hi_f(ah1));
        uint32_t al2 = bf16x2_of(v01.x - bf16lo_f(ah2), v01.y - bf16hi_f(ah2));
        uint32_t al3 = bf16x2_of(v11.x - bf16lo_f(ah3), v11.y - bf16hi_f(ah3));
        uint32_t al4 = bf16x2_of(v20.x - bf16lo_f(ah4), v20.y - bf16hi_f(ah4));
        uint32_t al5 = bf16x2_of(v30.x - bf16lo_f(ah5), v30.y - bf16hi_f(ah5));
        uint32_t al6 = bf16x2_of(v21.x - bf16lo_f(ah6), v21.y - bf16hi_f(ah6));
        uint32_t al7 = bf16x2_of(v31.x - bf16lo_f(ah7), v31.y - bf16hi_f(ah7));

        const uint32_t* wh = &sWh[gid * WSTRIDE + 8 * kt + tig];
        const uint32_t* wl = &sWl[gid * WSTRIDE + 8 * kt + tig];
        #pragma unroll
        for (int nt = 0; nt < 8; nt++) {
            uint32_t bh0 = wh[nt * 8 * WSTRIDE];
            uint32_t bh1 = wh[nt * 8 * WSTRIDE + 4];
            uint32_t bl0 = wl[nt * 8 * WSTRIDE];
            uint32_t bl1 = wl[nt * 8 * WSTRIDE + 4];
            MMA16816(acc[0][nt], ah0, ah1, ah2, ah3, bh0, bh1);
            MMA16816(acc[0][nt], al0, al1, al2, al3, bh0, bh1);
            MMA16816(acc[0][nt], ah0, ah1, ah2, ah3, bl0, bl1);
            MMA16816(acc[1][nt], ah4, ah5, ah6, ah7, bh0, bh1);
            MMA16816(acc[1][nt], al4, al5, al6, al7, bh0, bh1);
            MMA16816(acc[1][nt], ah4, ah5, ah6, ah7, bl0, bl1);
        }
    }

    // ---- epilogue: bias, store y, BN2 stats ---------------------------------
    #pragma unroll
    for (int nt = 0; nt < 8; nt++) {
        int col = 8 * nt + 2 * tig;
        float b0 = sBp[col], b1 = sBp[col + 1];

        float c0 = acc[0][nt][0] + b0, c1 = acc[0][nt][1] + b1;
        float c2 = acc[0][nt][2] + b0, c3 = acc[0][nt][3] + b1;
        float d0 = acc[1][nt][0] + b0, d1 = acc[1][nt][1] + b1;
        float d2 = acc[1][nt][2] + b0, d3 = acc[1][nt][3] + b1;

        *(float2*)&g_y[row0 * FHID + col]        = make_float2(c0, c1);
        *(float2*)&g_y[(row0 + 8) * FHID + col]  = make_float2(c2, c3);
        *(float2*)&g_y[(row0 + 16) * FHID + col] = make_float2(d0, d1);
        *(float2*)&g_y[(row0 + 24) * FHID + col] = make_float2(d2, d3);

        unsigned long long vs = pack2(c0 + c2 + d0 + d2, c1 + c3 + d1 + d3);
        unsigned long long vq = pack2(c0 * c0 + c2 * c2 + d0 * d0 + d2 * d2,
                                      c1 * c1 + c3 * c3 + d1 * d1 + d3 * d3);
        #pragma unroll
        for (int o = 4; o <= 16; o <<= 1) {           // reduce across gid bits
            vs = add2(vs, __shfl_xor_sync(0xffffffffu, vs, o));
            vq = add2(vq, __shfl_xor_sync(0xffffffffu, vq, o));
        }
        if (gid == 0) {
            float2 s2 = unpack2(vs), q2 = unpack2(vq);
            atomicAdd(&sS[col],     s2.x);
            atomicAdd(&sS[col + 1], s2.y);
            atomicAdd(&sQ[col],     q2.x);
            atomicAdd(&sQ[col + 1], q2.y);
        }
    }
    __syncthreads();
    if (tid < FHID) {
        atomicAdd(&g_sum2[tid], sS[tid]);
        atomicAdd(&g_sumsq2[tid], sQ[tid]);
    }
}

// ---------------- K4: finalize BN2 affine ----------------------------------
__global__ void k_fin2(const float* __restrict__ g2, const float* __restrict__ b2) {
    int tid = threadIdx.x;  // 64
    float inv = 1.f / (float)MROWS;
    float mu  = g_sum2[tid] * inv;
    float var = g_sumsq2[tid] * inv - mu * mu;
    float rs  = rsqrtf(var + EPSV);
    float sc  = g2[tid] * rs;
    g_sc2[tid] = sc;
    g_bi2[tid] = b2[tid] - mu * sc;
}

// ---------------- K5: s = leaky(bn2(y)) @ a  (row-pair packed) --------------
__global__ void k_rowdot(const float* __restrict__ a_vec) {
    __shared__ float sc[FHID], sb[FHID], sa[FHID];
    __shared__ float redS[8], redQ[8];
    int tid = threadIdx.x, lane = tid & 31, w = tid >> 5;  // 256 thr
    if (tid < FHID) { sc[tid] = g_sc2[tid]; sb[tid] = g_bi2[tid]; sa[tid] = a_vec[tid]; }
    __syncthreads();
    int h0 = 2 * lane, h1 = h0 + 1;
    float c0 = sc[h0], b0 = sb[h0], A0 = sa[h0];
    float c1 = sc[h1], b1 = sb[h1], A1 = sa[h1];
    float ps = 0.f, pq = 0.f;
    const int PAIRS = MROWS / 2;
    for (int p = blockIdx.x * 8 + w; p < PAIRS; p += gridDim.x * 8) {
        size_t r = 2 * (size_t)p;
        float2 vA = ((const float2*)(g_y + r * FHID))[lane];
        float2 vB = ((const float2*)(g_y + (r + 1) * FHID))[lane];
        float tA = A0 * leakyf(vA.x * c0 + b0) + A1 * leakyf(vA.y * c1 + b1);
        float tB = A0 * leakyf(vB.x * c0 + b0) + A1 * leakyf(vB.y * c1 + b1);
        unsigned long long t = pack2(tA, tB);
        #pragma unroll
        for (int o = 16; o; o >>= 1) t = add2(t, __shfl_xor_sync(0xffffffffu, t, o));
        if (lane == 0) {
            float2 s2 = unpack2(t);
            *(float2*)&g_s[r] = s2;
            ps += s2.x + s2.y;
            pq += s2.x * s2.x + s2.y * s2.y;
        }
    }
    if (lane == 0) { redS[w] = ps; redQ[w] = pq; }
    __syncthreads();
    if (tid == 0) {
        float S = 0.f, Q = 0.f;
        #pragma unroll
        for (int i = 0; i < 8; i++) { S += redS[i]; Q += redQ[i]; }
        atomicAdd(&g_s3[0], S);
        atomicAdd(&g_s3[1], Q);
    }
}

// ---------------- K6: finalize BN3 affine ----------------------------------
__global__ void k_fin3(const float* __restrict__ g3, const float* __restrict__ b3) {
    float inv = 1.f / (float)MROWS;
    float mu  = g_s3[0] * inv;
    float var = g_s3[1] * inv - mu * mu;
    float rs  = rsqrtf(var + EPSV);
    float c   = g3[0] * rs;
    g_eaff[0] = c;
    g_eaff[1] = b3[0] - mu * c;
}

// ---------------- K7: masked row softmax ------------------------------------
__global__ void k_softmax(const float* __restrict__ adj_mean, float* __restrict__ out) {
    __shared__ float redm[8], reds[8];
    int row = blockIdx.x, tid = threadIdx.x, lane = tid & 31, w = tid >> 5;
    float c3 = g_eaff[0], d3 = g_eaff[1];
    float4 sv = ((const float4*)(g_s + (size_t)row * NROW))[tid];
    float4 mv = ((const float4*)(adj_mean + (size_t)row * NROW))[tid];
    float v0 = (mv.x > 0.f) ? leakyf(sv.x * c3 + d3) : NEGV;
    float v1 = (mv.y > 0.f) ? leakyf(sv.y * c3 + d3) : NEGV;
    float v2 = (mv.z > 0.f) ? leakyf(sv.z * c3 + d3) : NEGV;
    float v3 = (mv.w > 0.f) ? leakyf(sv.w * c3 + d3) : NEGV;

    float m = fmaxf(fmaxf(v0, v1), fmaxf(v2, v3));
    #pragma unroll
    for (int o = 16; o; o >>= 1) m = fmaxf(m, __shfl_xor_sync(0xffffffffu, m, o));
    if (lane == 0) redm[w] = m;
    __syncthreads();
    if (tid < 8) {
        float t = redm[tid];
        #pragma unroll
        for (int o = 4; o; o >>= 1) t = fmaxf(t, __shfl_xor_sync(0xffu, t, o));
        if (tid == 0) redm[0] = t;
    }
    __syncthreads();
    float rm = redm[0];

    float p0 = expf(v0 - rm), p1 = expf(v1 - rm), p2 = expf(v2 - rm), p3 = expf(v3 - rm);
    float s = p0 + p1 + p2 + p3;
    #pragma unroll
    for (int o = 16; o; o >>= 1) s += __shfl_xor_sync(0xffffffffu, s, o);
    if (lane == 0) reds[w] = s;
    __syncthreads();
    if (tid < 8) {
        float t = reds[tid];
        #pragma unroll
        for (int o = 4; o; o >>= 1) t += __shfl_xor_sync(0xffu, t, o);
        if (tid == 0) reds[0] = t;
    }
    __syncthreads();
    float invs = 1.f / reds[0];

    ((float4*)(out + (size_t)row * NROW))[tid] =
        make_float4(p0 * invs, p1 * invs, p2 * invs, p3 * invs);
}

// ---------------- launcher ---------------------------------------------------
extern "C" void kernel_launch(void* const* d_in, const int* in_sizes, int n_in,
                              void* d_out, int out_size) {
    const float* adj      = (const float*)d_in[0];
    const float* adj_mean = (const float*)d_in[1];
    const float* W        = (const float*)d_in[2];
    const float* a        = (const float*)d_in[3];
    const float* gamma1   = (const float*)d_in[4];
    const float* beta1    = (const float*)d_in[5];
    const float* gamma2   = (const float*)d_in[6];
    const float* beta2    = (const float*)d_in[7];
    const float* gamma3   = (const float*)d_in[8];
    const float* beta3    = (const float*)d_in[9];
    float* out            = (float*)d_out;

    k_zero<<<1, 128>>>();
    k_colstats<<<2048, 256>>>((const float4*)adj);
    k_fin1<<<1, 128>>>(W, gamma1, beta1);
    k_gemm_mma<<<MROWS / GTM, 256>>>(adj);
    k_fin2<<<1, 64>>>(gamma2, beta2);
    k_rowdot<<<2048, 256>>>(a);
    k_fin3<<<1, 1>>>(gamma3, beta3);
    k_softmax<<<NROW, 256>>>(adj_mean, out);
}

// round 10
// speedup vs baseline: 2.6501x; 1.0670x over previous
#include <cuda_runtime.h>
#include <cuda_bf16.h>
#include <cstdint>

#define FIN   128
#define FHID  64
#define NROW  1024
#define MROWS (NROW*NROW)
#define EPSV  1e-5f
#define ALPHA 0.2f
#define NEGV  -9e15f

#define GTM     256          // rows per GEMM CTA (8 warps x 32-row tiles)
#define WSTRIDE 68           // words per W-row in smem (68 mod 32 = 4 -> conflict-free)

// ---------------- scratch ----------------------------------------------------
__device__ float g_sum1[FIN],  g_sumsq1[FIN];
__device__ float g_bp[FHID];
__device__ __nv_bfloat16 g_WpT_hi[FHID*FIN];   // [n][k] K-major
__device__ __nv_bfloat16 g_WpT_lo[FHID*FIN];
__device__ float g_sum2[FHID], g_sumsq2[FHID];
__device__ float g_sc2[FHID],  g_bi2[FHID];
__device__ float g_s3[2];
__device__ float g_eaff[2];
// y stored in FRAGMENT-NATIVE layout: [cta*8+warp][i=0..15][lane][4]
__device__ float g_y[(size_t)MROWS*FHID];
__device__ float g_s[MROWS];                   // 4 MB pre-BN3 scalars

// ---------------- helpers ----------------------------------------------------
__device__ __forceinline__ unsigned long long pack2(float lo, float hi) {
    unsigned long long r;
    asm("mov.b64 %0, {%1, %2};" : "=l"(r) : "f"(lo), "f"(hi));
    return r;
}
__device__ __forceinline__ float2 unpack2(unsigned long long v) {
    float2 f;
    asm("mov.b64 {%0, %1}, %2;" : "=f"(f.x), "=f"(f.y) : "l"(v));
    return f;
}
__device__ __forceinline__ unsigned long long add2(unsigned long long a,
                                                   unsigned long long b) {
    unsigned long long d;
    asm("add.rn.f32x2 %0, %1, %2;" : "=l"(d) : "l"(a), "l"(b));
    return d;
}
__device__ __forceinline__ float leakyf(float v) { return v >= 0.f ? v : ALPHA * v; }

// bf16x2 pack: low half <- a, high half <- b
__device__ __forceinline__ uint32_t bf16x2_of(float a, float b) {
    uint32_t d;
    asm("cvt.rn.bf16x2.f32 %0, %1, %2;" : "=r"(d) : "f"(b), "f"(a));
    return d;
}
__device__ __forceinline__ float bf16lo_f(uint32_t w) { return __uint_as_float(w << 16); }
__device__ __forceinline__ float bf16hi_f(uint32_t w) { return __uint_as_float(w & 0xFFFF0000u); }

// m16n8k16 row.col bf16 -> f32 accumulate-in-place
#define MMA16816(c, a0, a1, a2, a3, b0, b1)                                       \
    asm volatile("mma.sync.aligned.m16n8k16.row.col.f32.bf16.bf16.f32 "           \
                 "{%0,%1,%2,%3}, {%4,%5,%6,%7}, {%8,%9}, {%0,%1,%2,%3};"          \
                 : "+f"((c)[0]), "+f"((c)[1]), "+f"((c)[2]), "+f"((c)[3])         \
                 : "r"(a0), "r"(a1), "r"(a2), "r"(a3), "r"(b0), "r"(b1))

// ---------------- K0: zero accumulators ------------------------------------
__global__ void k_zero() {
    int t = threadIdx.x;  // 128 threads
    if (t < FIN)  { g_sum1[t] = 0.f; g_sumsq1[t] = 0.f; }
    if (t < FHID) { g_sum2[t] = 0.f; g_sumsq2[t] = 0.f; }
    if (t < 2)    { g_s3[t] = 0.f; }
}

// ---------------- K1: per-feature sum / sumsq over 1M rows ------------------
__global__ void k_colstats(const float4* __restrict__ x) {
    __shared__ float shS[8 * FIN], shQ[8 * FIN];
    int tid = threadIdx.x, lane = tid & 31, w = tid >> 5;
    float4 s = make_float4(0.f, 0.f, 0.f, 0.f);
    float4 q = make_float4(0.f, 0.f, 0.f, 0.f);
    for (int r = blockIdx.x * 8 + w; r < MROWS; r += gridDim.x * 8) {
        float4 v = x[(size_t)r * (FIN / 4) + lane];
        s.x += v.x; s.y += v.y; s.z += v.z; s.w += v.w;
        q.x += v.x * v.x; q.y += v.y * v.y; q.z += v.z * v.z; q.w += v.w * v.w;
    }
    ((float4*)(shS + w * FIN))[lane] = s;
    ((float4*)(shQ + w * FIN))[lane] = q;
    __syncthreads();
    if (tid < FIN) {
        float a = 0.f, b = 0.f;
        #pragma unroll
        for (int ww = 0; ww < 8; ww++) { a += shS[ww * FIN + tid]; b += shQ[ww * FIN + tid]; }
        atomicAdd(&g_sum1[tid], a);
        atomicAdd(&g_sumsq1[tid], b);
    }
}

// ---------------- K2: fold BN1 into W; emit bf16-split W^T ------------------
__global__ void k_fin1(const float* __restrict__ W, const float* __restrict__ g1,
                       const float* __restrict__ b1) {
    __shared__ float s1[FIN], t1[FIN];
    int tid = threadIdx.x;  // 128 threads, tid = k
    float inv = 1.f / (float)MROWS;
    float mu  = g_sum1[tid] * inv;
    float var = g_sumsq1[tid] * inv - mu * mu;
    float rs  = rsqrtf(var + EPSV);
    float sc  = g1[tid] * rs;
    s1[tid] = sc;
    t1[tid] = b1[tid] - mu * sc;
    __syncthreads();
    float sv = s1[tid];
    for (int n = 0; n < FHID; n++) {
        float wv = sv * W[tid * FHID + n];
        __nv_bfloat16 bh = __float2bfloat16_rn(wv);
        float bhf = __bfloat162float(bh);
        __nv_bfloat16 bl = __float2bfloat16_rn(wv - bhf);
        g_WpT_hi[n * FIN + tid] = bh;
        g_WpT_lo[n * FIN + tid] = bl;
    }
    if (tid < FHID) {
        float acc = 0.f;
        for (int f = 0; f < FIN; f++) acc += t1[f] * W[f * FHID + tid];
        g_bp[tid] = acc;
    }
}

// ---------------- K3: mma.sync GEMM  y = x@Wp + bp  (+ y stats) -------------
// 256 thr / 8 warps; CTA tile 256x64; warp tile 32x64 (2 m-tiles).
// y is dumped in fragment-native warp-interleaved layout: every STG request
// is 512B contiguous (4 lines) instead of spanning 8 rows.
__global__ __launch_bounds__(256, 2) void k_gemm_mma(const float* __restrict__ x) {
    __shared__ uint32_t sWh[FHID * WSTRIDE], sWl[FHID * WSTRIDE];
    __shared__ float sS[FHID], sQ[FHID], sBp[FHID];

    int tid = threadIdx.x, lane = tid & 31, wid = tid >> 5;
    int gid = lane >> 2, tig = lane & 3;

    for (int i = tid; i < FHID * (FIN / 2); i += 256) {
        int n = i >> 6, w = i & 63;
        sWh[n * WSTRIDE + w] = ((const uint32_t*)g_WpT_hi)[n * (FIN / 2) + w];
        sWl[n * WSTRIDE + w] = ((const uint32_t*)g_WpT_lo)[n * (FIN / 2) + w];
    }
    if (tid < FHID) { sS[tid] = 0.f; sQ[tid] = 0.f; sBp[tid] = g_bp[tid]; }
    __syncthreads();

    size_t blockRow = (size_t)blockIdx.x * GTM;
    size_t row0 = blockRow + 32 * wid + gid;           // rows: row0, +8, +16, +24
    const float* xr0 = x + row0 * FIN;
    const float* xr1 = x + (row0 + 8) * FIN;
    const float* xr2 = x + (row0 + 16) * FIN;
    const float* xr3 = x + (row0 + 24) * FIN;

    float acc[2][8][4];
    #pragma unroll
    for (int m = 0; m < 2; m++)
        #pragma unroll
        for (int nt = 0; nt < 8; nt++)
            #pragma unroll
            for (int j = 0; j < 4; j++) acc[m][nt][j] = 0.f;

    #pragma unroll
    for (int kt = 0; kt < 8; kt++) {
        int k0 = 16 * kt + 2 * tig;
        float2 v00 = *(const float2*)(xr0 + k0);
        float2 v10 = *(const float2*)(xr1 + k0);
        float2 v20 = *(const float2*)(xr2 + k0);
        float2 v30 = *(const float2*)(xr3 + k0);
        float2 v01 = *(const float2*)(xr0 + k0 + 8);
        float2 v11 = *(const float2*)(xr1 + k0 + 8);
        float2 v21 = *(const float2*)(xr2 + k0 + 8);
        float2 v31 = *(const float2*)(xr3 + k0 + 8);

        uint32_t ah0 = bf16x2_of(v00.x, v00.y);
        uint32_t ah1 = bf16x2_of(v10.x, v10.y);
        uint32_t ah2 = bf16x2_of(v01.x, v01.y);
        uint32_t ah3 = bf16x2_of(v11.x, v11.y);
        uint32_t ah4 = bf16x2_of(v20.x, v20.y);
        uint32_t ah5 = bf16x2_of(v30.x, v30.y);
        uint32_t ah6 = bf16x2_of(v21.x, v21.y);
        uint32_t ah7 = bf16x2_of(v31.x, v31.y);
        uint32_t al0 = bf16x2_of(v00.x - bf16lo_f(ah0), v00.y - bf16hi_f(ah0));
        uint32_t al1 = bf16x2_of(v10.x - bf16lo_f(ah1), v10.y - bf16hi_f(ah1));
        uint32_t al2 = bf16x2_of(v01.x - bf16lo_f(ah2), v01.y - bf16hi_f(ah2));
        uint32_t al3 = bf16x2_of(v11.x - bf16lo_f(ah3), v11.y - bf16hi_f(ah3));
        uint32_t al4 = bf16x2_of(v20.x - bf16lo_f(ah4), v20.y - bf16hi_f(ah4));
        uint32_t al5 = bf16x2_of(v30.x - bf16lo_f(ah5), v30.y - bf16hi_f(ah5));
        uint32_t al6 = bf16x2_of(v21.x - bf16lo_f(ah6), v21.y - bf16hi_f(ah6));
        uint32_t al7 = bf16x2_of(v31.x - bf16lo_f(ah7), v31.y - bf16hi_f(ah7));

        const uint32_t* wh = &sWh[gid * WSTRIDE + 8 * kt + tig];
        const uint32_t* wl = &sWl[gid * WSTRIDE + 8 * kt + tig];
        #pragma unroll
        for (int nt = 0; nt < 8; nt++) {
            uint32_t bh0 = wh[nt * 8 * WSTRIDE];
            uint32_t bh1 = wh[nt * 8 * WSTRIDE + 4];
            uint32_t bl0 = wl[nt * 8 * WSTRIDE];
            uint32_t bl1 = wl[nt * 8 * WSTRIDE + 4];
            MMA16816(acc[0][nt], ah0, ah1, ah2, ah3, bh0, bh1);
            MMA16816(acc[0][nt], al0, al1, al2, al3, bh0, bh1);
            MMA16816(acc[0][nt], ah0, ah1, ah2, ah3, bl0, bl1);
            MMA16816(acc[1][nt], ah4, ah5, ah6, ah7, bh0, bh1);
            MMA16816(acc[1][nt], al4, al5, al6, al7, bh0, bh1);
            MMA16816(acc[1][nt], ah4, ah5, ah6, ah7, bl0, bl1);
        }
    }

    // ---- epilogue: bias, fragment-native y dump, BN2 stats ------------------
    // dump layout: per warp 16 chunks of 128 floats; chunk i = m*8+nt,
    // thread stores float4 {c0,c1,c2,c3} at dump[i*128 + lane*4] (coalesced).
    float* dump = g_y + ((size_t)blockIdx.x * 8 + wid) * (16 * 128);
    #pragma unroll
    for (int nt = 0; nt < 8; nt++) {
        int col = 8 * nt + 2 * tig;
        float b0 = sBp[col], b1 = sBp[col + 1];

        float c0 = acc[0][nt][0] + b0, c1 = acc[0][nt][1] + b1;
        float c2 = acc[0][nt][2] + b0, c3 = acc[0][nt][3] + b1;
        float d0 = acc[1][nt][0] + b0, d1 = acc[1][nt][1] + b1;
        float d2 = acc[1][nt][2] + b0, d3 = acc[1][nt][3] + b1;

        *(float4*)(dump + (0 * 8 + nt) * 128 + lane * 4) = make_float4(c0, c1, c2, c3);
        *(float4*)(dump + (1 * 8 + nt) * 128 + lane * 4) = make_float4(d0, d1, d2, d3);

        unsigned long long vs = pack2(c0 + c2 + d0 + d2, c1 + c3 + d1 + d3);
        unsigned long long vq = pack2(c0 * c0 + c2 * c2 + d0 * d0 + d2 * d2,
                                      c1 * c1 + c3 * c3 + d1 * d1 + d3 * d3);
        #pragma unroll
        for (int o = 4; o <= 16; o <<= 1) {           // reduce across gid bits
            vs = add2(vs, __shfl_xor_sync(0xffffffffu, vs, o));
            vq = add2(vq, __shfl_xor_sync(0xffffffffu, vq, o));
        }
        if (gid == 0) {
            float2 s2 = unpack2(vs), q2 = unpack2(vq);
            atomicAdd(&sS[col],     s2.x);
            atomicAdd(&sS[col + 1], s2.y);
            atomicAdd(&sQ[col],     q2.x);
            atomicAdd(&sQ[col + 1], q2.y);
        }
    }
    __syncthreads();
    if (tid < FHID) {
        atomicAdd(&g_sum2[tid], sS[tid]);
        atomicAdd(&g_sumsq2[tid], sQ[tid]);
    }
}

// ---------------- K4: finalize BN2 affine ----------------------------------
__global__ void k_fin2(const float* __restrict__ g2, const float* __restrict__ b2) {
    int tid = threadIdx.x;  // 64
    float inv = 1.f / (float)MROWS;
    float mu  = g_sum2[tid] * inv;
    float var = g_sumsq2[tid] * inv - mu * mu;
    float rs  = rsqrtf(var + EPSV);
    float sc  = g2[tid] * rs;
    g_sc2[tid] = sc;
    g_bi2[tid] = b2[tid] - mu * sc;
}

// ---------------- K5: s = leaky(bn2(y)) @ a, fragment-layout consumer -------
// Mirrors gemm geometry: 4096 blocks x 256 thr; thread reads back exactly the
// 16 float4s its gemm counterpart wrote (coalesced), finishes rows via 2
// tig-shuffles, writes g_s + accumulates BN3 stats.
__global__ __launch_bounds__(256) void k_rowdot(const float* __restrict__ a_vec) {
    __shared__ float sc[FHID], sb[FHID], sa[FHID];
    __shared__ float redS[8], redQ[8];
    int tid = threadIdx.x, lane = tid & 31, w = tid >> 5;
    int gid = lane >> 2, tig = lane & 3;
    if (tid < FHID) { sc[tid] = g_sc2[tid]; sb[tid] = g_bi2[tid]; sa[tid] = a_vec[tid]; }
    __syncthreads();

    const float* dump = g_y + ((size_t)blockIdx.x * 8 + w) * (16 * 128);
    float p0 = 0.f, p1 = 0.f, p2 = 0.f, p3 = 0.f;   // rows gid, +8, +16, +24
    #pragma unroll
    for (int nt = 0; nt < 8; nt++) {
        int col = 8 * nt + 2 * tig;
        float A0 = sa[col], C0 = sc[col], B0 = sb[col];
        float A1 = sa[col + 1], C1 = sc[col + 1], B1 = sb[col + 1];
        float4 v = *(const float4*)(dump + nt * 128 + lane * 4);          // m=0
        float4 u = *(const float4*)(dump + (8 + nt) * 128 + lane * 4);    // m=1
        p0 += A0 * leakyf(v.x * C0 + B0) + A1 * leakyf(v.y * C1 + B1);
        p1 += A0 * leakyf(v.z * C0 + B0) + A1 * leakyf(v.w * C1 + B1);
        p2 += A0 * leakyf(u.x * C0 + B0) + A1 * leakyf(u.y * C1 + B1);
        p3 += A0 * leakyf(u.z * C0 + B0) + A1 * leakyf(u.w * C1 + B1);
    }
    unsigned long long t0 = pack2(p0, p1), t1 = pack2(p2, p3);
    t0 = add2(t0, __shfl_xor_sync(0xffffffffu, t0, 1));
    t0 = add2(t0, __shfl_xor_sync(0xffffffffu, t0, 2));
    t1 = add2(t1, __shfl_xor_sync(0xffffffffu, t1, 1));
    t1 = add2(t1, __shfl_xor_sync(0xffffffffu, t1, 2));

    float ps = 0.f, pq = 0.f;
    if (tig == 0) {
        float2 s0 = unpack2(t0), s1 = unpack2(t1);
        size_t base = (size_t)blockIdx.x * GTM + 32 * w + gid;
        g_s[base]      = s0.x;
        g_s[base + 8]  = s0.y;
        g_s[base + 16] = s1.x;
        g_s[base + 24] = s1.y;
        ps = s0.x + s0.y + s1.x + s1.y;
        pq = s0.x * s0.x + s0.y * s0.y + s1.x * s1.x + s1.y * s1.y;
    }
    #pragma unroll
    for (int o = 16; o; o >>= 1) {
        ps += __shfl_xor_sync(0xffffffffu, ps, o);
        pq += __shfl_xor_sync(0xffffffffu, pq, o);
    }
    if (lane == 0) { redS[w] = ps; redQ[w] = pq; }
    __syncthreads();
    if (tid == 0) {
        float S = 0.f, Q = 0.f;
        #pragma unroll
        for (int i = 0; i < 8; i++) { S += redS[i]; Q += redQ[i]; }
        atomicAdd(&g_s3[0], S);
        atomicAdd(&g_s3[1], Q);
    }
}

// ---------------- K6: finalize BN3 affine ----------------------------------
__global__ void k_fin3(const float* __restrict__ g3, const float* __restrict__ b3) {
    float inv = 1.f / (float)MROWS;
    float mu  = g_s3[0] * inv;
    float var = g_s3[1] * inv - mu * mu;
    float rs  = rsqrtf(var + EPSV);
    float c   = g3[0] * rs;
    g_eaff[0] = c;
    g_eaff[1] = b3[0] - mu * c;
}

// ---------------- K7: masked row softmax ------------------------------------
__global__ void k_softmax(const float* __restrict__ adj_mean, float* __restrict__ out) {
    __shared__ float redm[8], reds[8];
    int row = blockIdx.x, tid = threadIdx.x, lane = tid & 31, w = tid >> 5;
    float c3 = g_eaff[0], d3 = g_eaff[1];
    float4 sv = ((const float4*)(g_s + (size_t)row * NROW))[tid];
    float4 mv = ((const float4*)(adj_mean + (size_t)row * NROW))[tid];
    float v0 = (mv.x > 0.f) ? leakyf(sv.x * c3 + d3) : NEGV;
    float v1 = (mv.y > 0.f) ? leakyf(sv.y * c3 + d3) : NEGV;
    float v2 = (mv.z > 0.f) ? leakyf(sv.z * c3 + d3) : NEGV;
    float v3 = (mv.w > 0.f) ? leakyf(sv.w * c3 + d3) : NEGV;

    float m = fmaxf(fmaxf(v0, v1), fmaxf(v2, v3));
    #pragma unroll
    for (int o = 16; o; o >>= 1) m = fmaxf(m, __shfl_xor_sync(0xffffffffu, m, o));
    if (lane == 0) redm[w] = m;
    __syncthreads();
    if (tid < 8) {
        float t = redm[tid];
        #pragma unroll
        for (int o = 4; o; o >>= 1) t = fmaxf(t, __shfl_xor_sync(0xffu, t, o));
        if (tid == 0) redm[0] = t;
    }
    __syncthreads();
    float rm = redm[0];

    float p0 = expf(v0 - rm), p1 = expf(v1 - rm), p2 = expf(v2 - rm), p3 = expf(v3 - rm);
    float s = p0 + p1 + p2 + p3;
    #pragma unroll
    for (int o = 16; o; o >>= 1) s += __shfl_xor_sync(0xffffffffu, s, o);
    if (lane == 0) reds[w] = s;
    __syncthreads();
    if (tid < 8) {
        float t = reds[tid];
        #pragma unroll
        for (int o = 4; o; o >>= 1) t += __shfl_xor_sync(0xffu, t, o);
        if (tid == 0) reds[0] = t;
    }
    __syncthreads();
    float invs = 1.f / reds[0];

    ((float4*)(out + (size_t)row * NROW))[tid] =
        make_float4(p0 * invs, p1 * invs, p2 * invs, p3 * invs);
}

// ---------------- launcher ---------------------------------------------------
extern "C" void kernel_launch(void* const* d_in, const int* in_sizes, int n_in,
                              void* d_out, int out_size) {
    const float* adj      = (const float*)d_in[0];
    const float* adj_mean = (const float*)d_in[1];
    const float* W        = (const float*)d_in[2];
    const float* a        = (const float*)d_in[3];
    const float* gamma1   = (const float*)d_in[4];
    const float* beta1    = (const float*)d_in[5];
    const float* gamma2   = (const float*)d_in[6];
    const float* beta2    = (const float*)d_in[7];
    const float* gamma3   = (const float*)d_in[8];
    const float* beta3    = (const float*)d_in[9];
    float* out            = (float*)d_out;

    k_zero<<<1, 128>>>();
    k_colstats<<<2048, 256>>>((const float4*)adj);
    k_fin1<<<1, 128>>>(W, gamma1, beta1);
    k_gemm_mma<<<MROWS / GTM, 256>>>(adj);
    k_fin2<<<1, 64>>>(gamma2, beta2);
    k_rowdot<<<MROWS / GTM, 256>>>(a);
    k_fin3<<<1, 1>>>(gamma3, beta3);
    k_softmax<<<NROW, 256>>>(adj_mean, out);
}

// round 12
// speedup vs baseline: 2.7137x; 1.0240x over previous
#include <cuda_runtime.h>
#include <cuda_bf16.h>
#include <cstdint>

#define FIN   128
#define FHID  64
#define NROW  1024
#define MROWS (NROW*NROW)
#define EPSV  1e-5f
#define ALPHA 0.2f
#define NEGV  -9e15f

#define GTM     256          // rows per GEMM CTA (8 warps x 32-row tiles)
#define WSTRIDE 68           // words per W-row in smem

// ---------------- scratch ----------------------------------------------------
__device__ float g_sum1[FIN],  g_sumsq1[FIN];
__device__ float g_bp[FHID];
__device__ __nv_bfloat16 g_WpT_hi[FHID*FIN];   // [n][k] K-major
__device__ __nv_bfloat16 g_WpT_lo[FHID*FIN];
__device__ float g_sum2[FHID], g_sumsq2[FHID];
__device__ float g_sc2[FHID],  g_bi2[FHID];
__device__ float g_s3[2];
__device__ float g_eaff[2];
// y stored in FRAGMENT-NATIVE layout: [cta*8+warp][i=0..15][lane][4]
__device__ float g_y[(size_t)MROWS*FHID];
__device__ float g_s[MROWS];                   // 4 MB pre-BN3 scalars

// ---------------- helpers ----------------------------------------------------
__device__ __forceinline__ unsigned long long pack2(float lo, float hi) {
    unsigned long long r;
    asm("mov.b64 %0, {%1, %2};" : "=l"(r) : "f"(lo), "f"(hi));
    return r;
}
__device__ __forceinline__ float2 unpack2(unsigned long long v) {
    float2 f;
    asm("mov.b64 {%0, %1}, %2;" : "=f"(f.x), "=f"(f.y) : "l"(v));
    return f;
}
__device__ __forceinline__ unsigned long long add2(unsigned long long a,
                                                   unsigned long long b) {
    unsigned long long d;
    asm("add.rn.f32x2 %0, %1, %2;" : "=l"(d) : "l"(a), "l"(b));
    return d;
}
__device__ __forceinline__ float leakyf(float v) { return v >= 0.f ? v : ALPHA * v; }

// bf16x2 pack: low half <- a, high half <- b
__device__ __forceinline__ uint32_t bf16x2_of(float a, float b) {
    uint32_t d;
    asm("cvt.rn.bf16x2.f32 %0, %1, %2;" : "=r"(d) : "f"(b), "f"(a));
    return d;
}
__device__ __forceinline__ float bf16lo_f(uint32_t w) { return __uint_as_float(w << 16); }
__device__ __forceinline__ float bf16hi_f(uint32_t w) { return __uint_as_float(w & 0xFFFF0000u); }

// m16n8k16 row.col bf16 -> f32 accumulate-in-place
#define MMA16816(c, a0, a1, a2, a3, b0, b1)                                       \
    asm volatile("mma.sync.aligned.m16n8k16.row.col.f32.bf16.bf16.f32 "           \
                 "{%0,%1,%2,%3}, {%4,%5,%6,%7}, {%8,%9}, {%0,%1,%2,%3};"          \
                 : "+f"((c)[0]), "+f"((c)[1]), "+f"((c)[2]), "+f"((c)[3])         \
                 : "r"(a0), "r"(a1), "r"(a2), "r"(a3), "r"(b0), "r"(b1))

// ---------------- K0: zero accumulators ------------------------------------
__global__ void k_zero() {
    int t = threadIdx.x;  // 128 threads
    if (t < FIN)  { g_sum1[t] = 0.f; g_sumsq1[t] = 0.f; }
    if (t < FHID) { g_sum2[t] = 0.f; g_sumsq2[t] = 0.f; }
    if (t < 2)    { g_s3[t] = 0.f; }
}

// ---------------- K1: per-feature sum / sumsq over 1M rows ------------------
__global__ void k_colstats(const float4* __restrict__ x) {
    __shared__ float shS[8 * FIN], shQ[8 * FIN];
    int tid = threadIdx.x, lane = tid & 31, w = tid >> 5;
    float4 s = make_float4(0.f, 0.f, 0.f, 0.f);
    float4 q = make_float4(0.f, 0.f, 0.f, 0.f);
    for (int r = blockIdx.x * 8 + w; r < MROWS; r += gridDim.x * 8) {
        float4 v = x[(size_t)r * (FIN / 4) + lane];
        s.x += v.x; s.y += v.y; s.z += v.z; s.w += v.w;
        q.x += v.x * v.x; q.y += v.y * v.y; q.z += v.z * v.z; q.w += v.w * v.w;
    }
    ((float4*)(shS + w * FIN))[lane] = s;
    ((float4*)(shQ + w * FIN))[lane] = q;
    __syncthreads();
    if (tid < FIN) {
        float a = 0.f, b = 0.f;
        #pragma unroll
        for (int ww = 0; ww < 8; ww++) { a += shS[ww * FIN + tid]; b += shQ[ww * FIN + tid]; }
        atomicAdd(&g_sum1[tid], a);
        atomicAdd(&g_sumsq1[tid], b);
    }
}

// ---------------- K2: fold BN1 into W; emit bf16-split W^T ------------------
__global__ void k_fin1(const float* __restrict__ W, const float* __restrict__ g1,
                       const float* __restrict__ b1) {
    __shared__ float s1[FIN], t1[FIN];
    int tid = threadIdx.x;  // 128 threads, tid = k
    float inv = 1.f / (float)MROWS;
    float mu  = g_sum1[tid] * inv;
    float var = g_sumsq1[tid] * inv - mu * mu;
    float rs  = rsqrtf(var + EPSV);
    float sc  = g1[tid] * rs;
    s1[tid] = sc;
    t1[tid] = b1[tid] - mu * sc;
    __syncthreads();
    float sv = s1[tid];
    for (int n = 0; n < FHID; n++) {
        float wv = sv * W[tid * FHID + n];
        __nv_bfloat16 bh = __float2bfloat16_rn(wv);
        float bhf = __bfloat162float(bh);
        __nv_bfloat16 bl = __float2bfloat16_rn(wv - bhf);
        g_WpT_hi[n * FIN + tid] = bh;
        g_WpT_lo[n * FIN + tid] = bl;
    }
    if (tid < FHID) {
        float acc = 0.f;
        for (int f = 0; f < FIN; f++) acc += t1[f] * W[f * FHID + tid];
        g_bp[tid] = acc;
    }
}

// ---------------- K3: mma.sync GEMM  y = x@Wp + bp  (+ y stats) -------------
// 256 thr / 8 warps; CTA tile 256x64; warp tile 32x64 (2 m-tiles).
// k-permuted fragments: within each k16 tile, thread tig owns physical
// k {16kt+4tig .. +3}: slot-pair0 <- {4tig,4tig+1}, slot-pair1 <- {4tig+2,4tig+3}.
// Applied identically to A (one float4 LDG per row) and B (one LDS.64 per
// operand) -> product unchanged, memory instructions halved.
__global__ __launch_bounds__(256, 2) void k_gemm_mma(const float* __restrict__ x) {
    __shared__ uint32_t sWh[FHID * WSTRIDE], sWl[FHID * WSTRIDE];
    __shared__ float sS[FHID], sQ[FHID], sBp[FHID];

    int tid = threadIdx.x, lane = tid & 31, wid = tid >> 5;
    int gid = lane >> 2, tig = lane & 3;

    for (int i = tid; i < FHID * (FIN / 2); i += 256) {
        int n = i >> 6, w = i & 63;
        sWh[n * WSTRIDE + w] = ((const uint32_t*)g_WpT_hi)[n * (FIN / 2) + w];
        sWl[n * WSTRIDE + w] = ((const uint32_t*)g_WpT_lo)[n * (FIN / 2) + w];
    }
    if (tid < FHID) { sS[tid] = 0.f; sQ[tid] = 0.f; sBp[tid] = g_bp[tid]; }
    __syncthreads();

    size_t blockRow = (size_t)blockIdx.x * GTM;
    size_t row0 = blockRow + 32 * wid + gid;           // rows: row0, +8, +16, +24
    const float* xr0 = x + row0 * FIN;
    const float* xr1 = x + (row0 + 8) * FIN;
    const float* xr2 = x + (row0 + 16) * FIN;
    const float* xr3 = x + (row0 + 24) * FIN;

    float acc[2][8][4];
    #pragma unroll
    for (int m = 0; m < 2; m++)
        #pragma unroll
        for (int nt = 0; nt < 8; nt++)
            #pragma unroll
            for (int j = 0; j < 4; j++) acc[m][nt][j] = 0.f;

    #pragma unroll
    for (int kt = 0; kt < 8; kt++) {
        int k0 = 16 * kt + 4 * tig;
        float4 v0 = *(const float4*)(xr0 + k0);   // rows gid / +8 / +16 / +24
        float4 v1 = *(const float4*)(xr1 + k0);
        float4 v2 = *(const float4*)(xr2 + k0);
        float4 v3 = *(const float4*)(xr3 + k0);

        // m-tile 0 fragments (a0,a1 = slot-pair0 rows r,r+8; a2,a3 = slot-pair1)
        uint32_t a0h = bf16x2_of(v0.x, v0.y), a2h = bf16x2_of(v0.z, v0.w);
        uint32_t a1h = bf16x2_of(v1.x, v1.y), a3h = bf16x2_of(v1.z, v1.w);
        uint32_t a4h = bf16x2_of(v2.x, v2.y), a6h = bf16x2_of(v2.z, v2.w);
        uint32_t a5h = bf16x2_of(v3.x, v3.y), a7h = bf16x2_of(v3.z, v3.w);
        uint32_t a0l = bf16x2_of(v0.x - bf16lo_f(a0h), v0.y - bf16hi_f(a0h));
        uint32_t a2l = bf16x2_of(v0.z - bf16lo_f(a2h), v0.w - bf16hi_f(a2h));
        uint32_t a1l = bf16x2_of(v1.x - bf16lo_f(a1h), v1.y - bf16hi_f(a1h));
        uint32_t a3l = bf16x2_of(v1.z - bf16lo_f(a3h), v1.w - bf16hi_f(a3h));
        uint32_t a4l = bf16x2_of(v2.x - bf16lo_f(a4h), v2.y - bf16hi_f(a4h));
        uint32_t a6l = bf16x2_of(v2.z - bf16lo_f(a6h), v2.w - bf16hi_f(a6h));
        uint32_t a5l = bf16x2_of(v3.x - bf16lo_f(a5h), v3.y - bf16hi_f(a5h));
        uint32_t a7l = bf16x2_of(v3.z - bf16lo_f(a7h), v3.w - bf16hi_f(a7h));

        // B: words 8kt+2tig, +1 = physical k {16kt+4tig..+3} for col 8nt+gid
        const uint32_t* wh = &sWh[gid * WSTRIDE + 8 * kt + 2 * tig];
        const uint32_t* wl = &sWl[gid * WSTRIDE + 8 * kt + 2 * tig];
        #pragma unroll
        for (int nt = 0; nt < 8; nt++) {
            uint2 bh = *(const uint2*)&wh[nt * 8 * WSTRIDE];
            uint2 bl = *(const uint2*)&wl[nt * 8 * WSTRIDE];
            MMA16816(acc[0][nt], a0h, a1h, a2h, a3h, bh.x, bh.y);
            MMA16816(acc[0][nt], a0l, a1l, a2l, a3l, bh.x, bh.y);
            MMA16816(acc[0][nt], a0h, a1h, a2h, a3h, bl.x, bl.y);
            MMA16816(acc[1][nt], a4h, a5h, a6h, a7h, bh.x, bh.y);
            MMA16816(acc[1][nt], a4l, a5l, a6l, a7l, bh.x, bh.y);
            MMA16816(acc[1][nt], a4h, a5h, a6h, a7h, bl.x, bl.y);
        }
    }

    // ---- epilogue: bias, fragment-native y dump, BN2 stats ------------------
    float* dump = g_y + ((size_t)blockIdx.x * 8 + wid) * (16 * 128);
    #pragma unroll
    for (int nt = 0; nt < 8; nt++) {
        int col = 8 * nt + 2 * tig;
        float b0 = sBp[col], b1 = sBp[col + 1];

        float c0 = acc[0][nt][0] + b0, c1 = acc[0][nt][1] + b1;
        float c2 = acc[0][nt][2] + b0, c3 = acc[0][nt][3] + b1;
        float d0 = acc[1][nt][0] + b0, d1 = acc[1][nt][1] + b1;
        float d2 = acc[1][nt][2] + b0, d3 = acc[1][nt][3] + b1;

        *(float4*)(dump + (0 * 8 + nt) * 128 + lane * 4) = make_float4(c0, c1, c2, c3);
        *(float4*)(dump + (1 * 8 + nt) * 128 + lane * 4) = make_float4(d0, d1, d2, d3);

        unsigned long long vs = pack2(c0 + c2 + d0 + d2, c1 + c3 + d1 + d3);
        unsigned long long vq = pack2(c0 * c0 + c2 * c2 + d0 * d0 + d2 * d2,
                                      c1 * c1 + c3 * c3 + d1 * d1 + d3 * d3);
        #pragma unroll
        for (int o = 4; o <= 16; o <<= 1) {           // reduce across gid bits
            vs = add2(vs, __shfl_xor_sync(0xffffffffu, vs, o));
            vq = add2(vq, __shfl_xor_sync(0xffffffffu, vq, o));
        }
        if (gid == 0) {
            float2 s2 = unpack2(vs), q2 = unpack2(vq);
            atomicAdd(&sS[col],     s2.x);
            atomicAdd(&sS[col + 1], s2.y);
            atomicAdd(&sQ[col],     q2.x);
            atomicAdd(&sQ[col + 1], q2.y);
        }
    }
    __syncthreads();
    if (tid < FHID) {
        atomicAdd(&g_sum2[tid], sS[tid]);
        atomicAdd(&g_sumsq2[tid], sQ[tid]);
    }
}

// ---------------- K4: finalize BN2 affine ----------------------------------
__global__ void k_fin2(const float* __restrict__ g2, const float* __restrict__ b2) {
    int tid = threadIdx.x;  // 64
    float inv = 1.f / (float)MROWS;
    float mu  = g_sum2[tid] * inv;
    float var = g_sumsq2[tid] * inv - mu * mu;
    float rs  = rsqrtf(var + EPSV);
    float sc  = g2[tid] * rs;
    g_sc2[tid] = sc;
    g_bi2[tid] = b2[tid] - mu * sc;
}

// ---------------- K5: s = leaky(bn2(y)) @ a, fragment-layout consumer -------
__global__ __launch_bounds__(256) void k_rowdot(const float* __restrict__ a_vec) {
    __shared__ float sc[FHID], sb[FHID], sa[FHID];
    __shared__ float redS[8], redQ[8];
    int tid = threadIdx.x, lane = tid & 31, w = tid >> 5;
    int gid = lane >> 2, tig = lane & 3;
    if (tid < FHID) { sc[tid] = g_sc2[tid]; sb[tid] = g_bi2[tid]; sa[tid] = a_vec[tid]; }
    __syncthreads();

    const float* dump = g_y + ((size_t)blockIdx.x * 8 + w) * (16 * 128);
    float p0 = 0.f, p1 = 0.f, p2 = 0.f, p3 = 0.f;   // rows gid, +8, +16, +24
    #pragma unroll
    for (int nt = 0; nt < 8; nt++) {
        int col = 8 * nt + 2 * tig;
        float A0 = sa[col], C0 = sc[col], B0 = sb[col];
        float A1 = sa[col + 1], C1 = sc[col + 1], B1 = sb[col + 1];
        float4 v = *(const float4*)(dump + nt * 128 + lane * 4);          // m=0
        float4 u = *(const float4*)(dump + (8 + nt) * 128 + lane * 4);    // m=1
        p0 += A0 * leakyf(v.x * C0 + B0) + A1 * leakyf(v.y * C1 + B1);
        p1 += A0 * leakyf(v.z * C0 + B0) + A1 * leakyf(v.w * C1 + B1);
        p2 += A0 * leakyf(u.x * C0 + B0) + A1 * leakyf(u.y * C1 + B1);
        p3 += A0 * leakyf(u.z * C0 + B0) + A1 * leakyf(u.w * C1 + B1);
    }
    unsigned long long t0 = pack2(p0, p1), t1 = pack2(p2, p3);
    t0 = add2(t0, __shfl_xor_sync(0xffffffffu, t0, 1));
    t0 = add2(t0, __shfl_xor_sync(0xffffffffu, t0, 2));
    t1 = add2(t1, __shfl_xor_sync(0xffffffffu, t1, 1));
    t1 = add2(t1, __shfl_xor_sync(0xffffffffu, t1, 2));

    float ps = 0.f, pq = 0.f;
    if (tig == 0) {
        float2 s0 = unpack2(t0), s1 = unpack2(t1);
        size_t base = (size_t)blockIdx.x * GTM + 32 * w + gid;
        g_s[base]      = s0.x;
        g_s[base + 8]  = s0.y;
        g_s[base + 16] = s1.x;
        g_s[base + 24] = s1.y;
        ps = s0.x + s0.y + s1.x + s1.y;
        pq = s0.x * s0.x + s0.y * s0.y + s1.x * s1.x + s1.y * s1.y;
    }
    #pragma unroll
    for (int o = 16; o; o >>= 1) {
        ps += __shfl_xor_sync(0xffffffffu, ps, o);
        pq += __shfl_xor_sync(0xffffffffu, pq, o);
    }
    if (lane == 0) { redS[w] = ps; redQ[w] = pq; }
    __syncthreads();
    if (tid == 0) {
        float S = 0.f, Q = 0.f;
        #pragma unroll
        for (int i = 0; i < 8; i++) { S += redS[i]; Q += redQ[i]; }
        atomicAdd(&g_s3[0], S);
        atomicAdd(&g_s3[1], Q);
    }
}

// ---------------- K6: finalize BN3 affine ----------------------------------
__global__ void k_fin3(const float* __restrict__ g3, const float* __restrict__ b3) {
    float inv = 1.f / (float)MROWS;
    float mu  = g_s3[0] * inv;
    float var = g_s3[1] * inv - mu * mu;
    float rs  = rsqrtf(var + EPSV);
    float c   = g3[0] * rs;
    g_eaff[0] = c;
    g_eaff[1] = b3[0] - mu * c;
}

// ---------------- K7: masked row softmax ------------------------------------
__global__ void k_softmax(const float* __restrict__ adj_mean, float* __restrict__ out) {
    __shared__ float redm[8], reds[8];
    int row = blockIdx.x, tid = threadIdx.x, lane = tid & 31, w = tid >> 5;
    float c3 = g_eaff[0], d3 = g_eaff[1];
    float4 sv = ((const float4*)(g_s + (size_t)row * NROW))[tid];
    float4 mv = ((const float4*)(adj_mean + (size_t)row * NROW))[tid];
    float v0 = (mv.x > 0.f) ? leakyf(sv.x * c3 + d3) : NEGV;
    float v1 = (mv.y > 0.f) ? leakyf(sv.y * c3 + d3) : NEGV;
    float v2 = (mv.z > 0.f) ? leakyf(sv.z * c3 + d3) : NEGV;
    float v3 = (mv.w > 0.f) ? leakyf(sv.w * c3 + d3) : NEGV;

    float m = fmaxf(fmaxf(v0, v1), fmaxf(v2, v3));
    #pragma unroll
    for (int o = 16; o; o >>= 1) m = fmaxf(m, __shfl_xor_sync(0xffffffffu, m, o));
    if (lane == 0) redm[w] = m;
    __syncthreads();
    if (tid < 8) {
        float t = redm[tid];
        #pragma unroll
        for (int o = 4; o; o >>= 1) t = fmaxf(t, __shfl_xor_sync(0xffu, t, o));
        if (tid == 0) redm[0] = t;
    }
    __syncthreads();
    float rm = redm[0];

    float p0 = expf(v0 - rm), p1 = expf(v1 - rm), p2 = expf(v2 - rm), p3 = expf(v3 - rm);
    float s = p0 + p1 + p2 + p3;
    #pragma unroll
    for (int o = 16; o; o >>= 1) s += __shfl_xor_sync(0xffffffffu, s, o);
    if (lane == 0) reds[w] = s;
    __syncthreads();
    if (tid < 8) {
        float t = reds[tid];
        #pragma unroll
        for (int o = 4; o; o >>= 1) t += __shfl_xor_sync(0xffu, t, o);
        if (tid == 0) reds[0] = t;
    }
    __syncthreads();
    float invs = 1.f / reds[0];

    ((float4*)(out + (size_t)row * NROW))[tid] =
        make_float4(p0 * invs, p1 * invs, p2 * invs, p3 * invs);
}

// ---------------- launcher ---------------------------------------------------
extern "C" void kernel_launch(void* const* d_in, const int* in_sizes, int n_in,
                              void* d_out, int out_size) {
    const float* adj      = (const float*)d_in[0];
    const float* adj_mean = (const float*)d_in[1];
    const float* W        = (const float*)d_in[2];
    const float* a        = (const float*)d_in[3];
    const float* gamma1   = (const float*)d_in[4];
    const float* beta1    = (const float*)d_in[5];
    const float* gamma2   = (const float*)d_in[6];
    const float* beta2    = (const float*)d_in[7];
    const float* gamma3   = (const float*)d_in[8];
    const float* beta3    = (const float*)d_in[9];
    float* out            = (float*)d_out;

    k_zero<<<1, 128>>>();
    k_colstats<<<2048, 256>>>((const float4*)adj);
    k_fin1<<<1, 128>>>(W, gamma1, beta1);
    k_gemm_mma<<<MROWS / GTM, 256>>>(adj);
    k_fin2<<<1, 64>>>(gamma2, beta2);
    k_rowdot<<<MROWS / GTM, 256>>>(a);
    k_fin3<<<1, 1>>>(gamma3, beta3);
    k_softmax<<<NROW, 256>>>(adj_mean, out);
}